// round 9
// baseline (speedup 1.0000x reference)
#include <cuda_runtime.h>
#include <cstdint>

#define DEV_INLINE __device__ __forceinline__

// Problem constants
constexpr int B  = 32;
constexpr int S  = 512;
constexpr int D  = 512;
constexpr int NS = 5;

// Recurrent kernel tiling
constexpr int RANKS     = 8;            // CTAs per cluster
constexpr int BPC       = 2;            // batches per cluster
constexpr int NCLUSTERS = B / BPC;      // 16
constexpr int COLS      = D / RANKS;    // 64 columns per CTA
constexpr int RTHREADS  = 512;

// s-exchange tx budget (bytes); g-exchange is now a counting barrier
constexpr uint32_t TX_S = 320;            // (64 pre + 16 critical) * 4B
constexpr uint32_t GCNT = 16;             // 2 warps * 8 src CTAs arrive per step

// Scratch (static device arrays; no allocations allowed)
__device__ float g_A[(size_t)B * S * D];       // H @ W1
__device__ float g_C[(size_t)B * S * D];       // H @ W2

// ---------- helpers ----------
DEV_INLINE uint64_t pack2(float lo, float hi) {
    uint64_t r; asm("mov.b64 %0, {%1, %2};" : "=l"(r) : "f"(lo), "f"(hi)); return r;
}
DEV_INLINE void unpack2(uint64_t v, float& lo, float& hi) {
    asm("mov.b64 {%0, %1}, %2;" : "=f"(lo), "=f"(hi) : "l"(v));
}
DEV_INLINE uint64_t fma2(uint64_t a, uint64_t b, uint64_t c) {
    uint64_t d; asm("fma.rn.f32x2 %0, %1, %2, %3;" : "=l"(d) : "l"(a), "l"(b), "l"(c));
    return d;
}
DEV_INLINE uint64_t add2(uint64_t a, uint64_t b) {
    uint64_t d; asm("add.rn.f32x2 %0, %1, %2;" : "=l"(d) : "l"(a), "l"(b));
    return d;
}
DEV_INLINE uint32_t su32(const void* p) {
    uint32_t a;
    asm("{ .reg .u64 t; cvta.to.shared.u64 t, %1; cvt.u32.u64 %0, t; }" : "=r"(a) : "l"(p));
    return a;
}
DEV_INLINE uint32_t mapa_u32(uint32_t a, int rank) {
    uint32_t r; asm("mapa.shared::cluster.u32 %0, %1, %2;" : "=r"(r) : "r"(a), "r"(rank));
    return r;
}
// Remote store with mbarrier tx-completion (s-exchange only)
DEV_INLINE void stasync_b32(uint32_t daddr, uint32_t mbar, int rank, uint32_t v) {
    asm volatile(
        "{ .reg .b32 rd, rm;\n\t"
        "mapa.shared::cluster.u32 rd, %0, %2;\n\t"
        "mapa.shared::cluster.u32 rm, %1, %2;\n\t"
        "st.async.shared::cluster.mbarrier::complete_tx::bytes.b32 [rd], %3, [rm]; }"
        :: "r"(daddr), "r"(mbar), "r"(rank), "r"(v) : "memory");
}
// Plain remote DSMEM store (pre-mapa'd address)
DEV_INLINE void stc_b64_pre(uint32_t rdaddr, uint64_t v) {
    asm volatile("st.shared::cluster.b64 [%0], %1;"
                 :: "r"(rdaddr), "l"(v) : "memory");
}
// Remote arrive with cluster-scope release (pre-mapa'd address).
// Cumulative release: orders this warp's prior remote stores (after syncwarp).
DEV_INLINE void arrive_remote(uint32_t rmbar) {
    asm volatile("mbarrier.arrive.release.cluster.shared::cluster.b64 _, [%0];"
                 :: "r"(rmbar) : "memory");
}
DEV_INLINE void mbar_init(uint32_t a, uint32_t cnt) {
    asm volatile("mbarrier.init.shared.b64 [%0], %1;" :: "r"(a), "r"(cnt) : "memory");
}
DEV_INLINE void mbar_arrive_expect(uint32_t a, uint32_t tx) {
    asm volatile("mbarrier.arrive.expect_tx.shared.b64 _, [%0], %1;"
                 :: "r"(a), "r"(tx) : "memory");
}
// cta-scope acquire wait (s-exchange: st.async complete_tx into local smem)
DEV_INLINE void mbar_wait(uint32_t mbar, uint32_t parity) {
    asm volatile(
        "{\n\t"
        ".reg .pred P;\n\t"
        "WAIT_%=:\n\t"
        "mbarrier.try_wait.parity.acquire.cta.shared::cta.b64 P, [%0], %1, 0x989680;\n\t"
        "@P bra.uni DONE_%=;\n\t"
        "bra.uni WAIT_%=;\n\t"
        "DONE_%=:\n\t"
        "}"
        :: "r"(mbar), "r"(parity) : "memory");
}
// cluster-scope acquire wait (g-exchange: pairs with remote release-arrive)
DEV_INLINE void mbar_wait_cl(uint32_t mbar, uint32_t parity) {
    asm volatile(
        "{\n\t"
        ".reg .pred P;\n\t"
        "WAIT_%=:\n\t"
        "mbarrier.try_wait.parity.acquire.cluster.shared::cta.b64 P, [%0], %1, 0x989680;\n\t"
        "@P bra.uni DONE_%=;\n\t"
        "bra.uni WAIT_%=;\n\t"
        "DONE_%=:\n\t"
        "}"
        :: "r"(mbar), "r"(parity) : "memory");
}
DEV_INLINE void cluster_sync() {
    asm volatile("barrier.cluster.arrive.aligned;" ::: "memory");
    asm volatile("barrier.cluster.wait.aligned;"   ::: "memory");
}
// fast tanh via __expf, clamped so exp never overflows
DEV_INLINE float ftanh(float x) {
    x = fminf(15.f, fmaxf(-15.f, x));
    float e = __expf(x + x);
    return __fdividef(e - 1.f, e + 1.f);
}

// ============================================================
// Precompute: A = H @ W1, C = H @ W2   (fp32, f32x2 FMAs)
// (R5 version — known-good baseline)
// ============================================================
constexpr int PM = 128, PN = 128, PK = 16;

__global__ __launch_bounds__(256) void precompute_kernel(
    const float* __restrict__ Hm,
    const float* __restrict__ W1,
    const float* __restrict__ W2)
{
    __shared__ float As[PK][PM];
    __shared__ float Bs[PK][PN];

    const int tid   = threadIdx.x;
    const int which = blockIdx.y >> 2;
    const int n0    = (blockIdx.y & 3) * PN;
    const int m0    = blockIdx.x * PM;
    const float* W  = which ? W2 : W1;
    float* OUT      = which ? g_C : g_A;

    const int tx = tid & 15;
    const int ty = tid >> 4;

    uint64_t acc[8][4];
    #pragma unroll
    for (int i = 0; i < 8; i++)
        #pragma unroll
        for (int j = 0; j < 4; j++) acc[i][j] = 0ull;

    for (int kt = 0; kt < 512; kt += PK) {
        #pragma unroll
        for (int i = 0; i < 2; i++) {
            int idx4 = i * 256 + tid;
            int m  = idx4 >> 2;
            int kq = (idx4 & 3) * 4;
            float4 vv = *(const float4*)&Hm[(size_t)(m0 + m) * 512 + kt + kq];
            As[kq + 0][m] = vv.x; As[kq + 1][m] = vv.y;
            As[kq + 2][m] = vv.z; As[kq + 3][m] = vv.w;
        }
        #pragma unroll
        for (int i = 0; i < 2; i++) {
            int idx4 = i * 256 + tid;
            int n4 = (idx4 & 31) * 4;
            int k  = idx4 >> 5;
            *(float4*)&Bs[k][n4] = *(const float4*)&W[(size_t)(kt + k) * 512 + n0 + n4];
        }
        __syncthreads();

        #pragma unroll
        for (int k = 0; k < PK; k++) {
            float4 a0 = *(const float4*)&As[k][ty * 8];
            float4 a1 = *(const float4*)&As[k][ty * 8 + 4];
            float4 b0 = *(const float4*)&Bs[k][tx * 8];
            float4 b1 = *(const float4*)&Bs[k][tx * 8 + 4];
            float av[8] = {a0.x, a0.y, a0.z, a0.w, a1.x, a1.y, a1.z, a1.w};
            uint64_t bp[4];
            bp[0] = pack2(b0.x, b0.y); bp[1] = pack2(b0.z, b0.w);
            bp[2] = pack2(b1.x, b1.y); bp[3] = pack2(b1.z, b1.w);
            #pragma unroll
            for (int i = 0; i < 8; i++) {
                uint64_t ad = pack2(av[i], av[i]);
                #pragma unroll
                for (int j = 0; j < 4; j++)
                    acc[i][j] = fma2(ad, bp[j], acc[i][j]);
            }
        }
        __syncthreads();
    }

    #pragma unroll
    for (int i = 0; i < 8; i++) {
        int row = m0 + ty * 8 + i;
        float f0, f1, f2, f3, f4, f5, f6, f7;
        unpack2(acc[i][0], f0, f1); unpack2(acc[i][1], f2, f3);
        unpack2(acc[i][2], f4, f5); unpack2(acc[i][3], f6, f7);
        *(float4*)&OUT[(size_t)row * 512 + n0 + tx * 8]     = make_float4(f0, f1, f2, f3);
        *(float4*)&OUT[(size_t)row * 512 + n0 + tx * 8 + 4] = make_float4(f4, f5, f6, f7);
    }
}

// ============================================================
// Recurrent kernel: R8 base. ONE structural change:
// g-exchange = plain remote b64 stores + 1 release-arrive per warp
// (16-count mbarrier) instead of 1024 st.async tx-updates per step.
// ============================================================
__global__ __launch_bounds__(RTHREADS, 1) __cluster_dims__(RANKS, 1, 1)
void recurrent_kernel(const float* __restrict__ Hm,
                      const float* __restrict__ v,
                      const float* __restrict__ W3,
                      float* __restrict__ out)
{
    __shared__ float2   hdup[BPC][COLS];             // (hv,hv) per batch/own col
    __shared__ float    thist[NS][BPC][COLS];        // htilde history
    __shared__ float    ghist[NS][BPC][COLS];        // summed g history
    __shared__ uint64_t gpartB[RANKS][2][BPC][32];   // [src][khalf][bl][pair]
    __shared__ float    spart[2][BPC][NS][RANKS];    // logit partials, parity
    __shared__ float    pbufA[2][BPC * NS][COLS];    // prefetched g_A rows
    __shared__ float    pbufC[2][BPC][COLS];         // prefetched g_C rows
    __shared__ float    hbuf[2][BPC][COLS];          // prefetched H rows
    __shared__ float    vsm[COLS];
    __shared__ float    ssm[BPC * NS];
    __shared__ float    wsm[BPC][NS];
    __shared__ uint64_t mbars[6];                    // [0..1]=g ring, [2..5]=s ring

    const int tid  = threadIdx.x;
    const int warp = tid >> 5, lane = tid & 31;
    const int rank = blockIdx.x & (RANKS - 1);
    const int cl   = blockIdx.x >> 3;
    const int col0 = rank * COLS;
    const int b0   = cl * BPC;

    const uint32_t mg_base = su32(&mbars[0]);        // + 8*b  (b = 0,1)
    const uint32_t ms_base = su32(&mbars[2]);        // + 8*k  (k = 0..3)

    // ---- init mbarriers, then cluster-wide visibility ----
    if (tid == 0) {
        // g ring: pure counting barriers, 16 arrives (2 warps x 8 src CTAs)
        mbar_init(mg_base + 0, GCNT);
        mbar_init(mg_base + 8, GCNT);
        #pragma unroll
        for (int k = 0; k < 4; k++) {
            mbar_init(ms_base + 8 * k, 1);
            mbar_arrive_expect(ms_base + 8 * k, TX_S);
        }
    }
    if (tid < COLS) vsm[tid] = v[col0 + tid];
    for (int i = tid; i < NS * BPC * COLS; i += RTHREADS) {
        ((float*)ghist)[i] = 0.f;
        ((float*)thist)[i] = 0.f;
    }
    __syncthreads();
    cluster_sync();   // all mbarriers initialized before any remote traffic

    // ---- P3 identities: thread owns col pair (2p, 2p+1), k-half ----
    // NOTE: warp w (w<8) and warp 8+w push exclusively to rank w.
    const int pairIdx = tid & 255;
    const int khalf   = tid >> 8;
    const int gcol    = pairIdx * 2;
    const int gdst    = pairIdx >> 5;                // = warp & 7 (uniform per warp)
    const uint32_t grd0 = mapa_u32(su32(&gpartB[rank][khalf][0][pairIdx & 31]), gdst);
    const uint32_t grd1 = mapa_u32(su32(&gpartB[rank][khalf][1][pairIdx & 31]), gdst);
    uint32_t grm[2];
    grm[0] = mapa_u32(mg_base + 0, gdst);
    grm[1] = mapa_u32(mg_base + 8, gdst);

    // W3 slice: 32 k-rows x 2 adjacent cols, pair-packed
    uint64_t w3p[32];
    #pragma unroll
    for (int kk = 0; kk < 32; kk++)
        w3p[kk] = *(const uint64_t*)&W3[(size_t)(col0 + khalf * 32 + kk) * D + gcol];

    // loader ids (warps 10-15)
    const int lidx = tid - 320;
    const int lrow = lidx >> 4;            // 0..11
    const int lq   = (lidx & 15) * 4;
    const int lbl  = (lidx >> 4) & 1;

    // P1 ids
    const int p1bl = (warp < 10) ? warp / NS : 0;
    const int p1i  = (warp < 10) ? warp % NS : 0;
    const int d0   = lane * 2;
    uint32_t spush[2];
    spush[0] = su32(&spart[0][p1bl][p1i][rank]);
    spush[1] = su32(&spart[1][p1bl][p1i][rank]);

    // mbarrier phase parities
    int pg0 = 0, pg1 = 0;
    int ps0 = 0, ps1 = 0, ps2 = 0, ps3 = 0;

    // ---- prologue: load t=0 C/H rows ----
    if (warp >= 10) {
        if (lrow >= 10)
            *(float4*)&pbufC[0][lrow - 10][lq] =
                __ldcs((const float4*)&g_C[((size_t)(b0 + lrow - 10) * S + 0) * D + col0 + lq]);
        if (lidx < 32)
            *(float4*)&hbuf[0][lbl][lq] =
                *(const float4*)&Hm[((size_t)(b0 + lbl) * S + 0) * D + col0 + lq];
    }
    __syncthreads();

    // prologue P1-pre for t=0 (i<4 warps; all j<0 -> c-only)
    if (warp < 10 && p1i != NS - 1) {
        float2 c2 = *(float2*)&pbufC[0][p1bl][d0];
        float val = ftanh(c2.x) * vsm[d0] + ftanh(c2.y) * vsm[d0 + 1];
        #pragma unroll
        for (int o = 16; o > 0; o >>= 1)
            val += __shfl_down_sync(0xffffffffu, val, o);
        if (lane == 0) {
            #pragma unroll
            for (int r = 0; r < RANKS; r++)
                stasync_b32(spush[0], ms_base + 0, r, __float_as_uint(val));
        }
    }

    // prologue: issue LDGs for t=1
    float4 pvA = make_float4(0.f, 0.f, 0.f, 0.f);
    float4 pvH = make_float4(0.f, 0.f, 0.f, 0.f);
    int pfrow = -1; bool pfH = false;
    if (warp >= 10) {
        if (lrow < 10) {
            int jbl = lrow / NS, ji = lrow % NS, j = 1 - NS + ji;
            if (j >= 0) {
                pvA = __ldcs((const float4*)&g_A[((size_t)(b0 + jbl) * S + j) * D + col0 + lq]);
                pfrow = lrow;
            }
        } else {
            pvA = __ldcs((const float4*)&g_C[((size_t)(b0 + lrow - 10) * S + 1) * D + col0 + lq]);
            pfrow = lrow;
        }
        if (lidx < 32) {
            pvH = *(const float4*)&Hm[((size_t)(b0 + lbl) * S + 1) * D + col0 + lq];
            pfH = true;
        }
    }

    for (int t = 0; t < S; t++) {
        const int par = t & 1;
        const int sk  = t & 3;

        // ---- critical warps (4, 9): wait g(t-1), sum, logit, push s ----
        if (warp < 10 && p1i == NS - 1) {
            const int j = t - 1;
            if (j >= 0) {
                const int gb = j & 1;
                mbar_wait_cl(mg_base + 8 * gb, gb ? pg1 : pg0);
                if (gb) pg1 ^= 1; else pg0 ^= 1;
                // counting mbarrier: auto-resets, no re-arm
            }
            float2 c2 = *(float2*)&pbufC[par][p1bl][d0];
            float x0 = c2.x, x1 = c2.y;
            if (j >= 0) {
                float2 a2 = *(float2*)&pbufA[par][warp][d0];
                uint64_t s = 0ull;
                #pragma unroll
                for (int r = 0; r < RANKS; r++) {
                    s = add2(s, gpartB[r][0][p1bl][lane]);
                    s = add2(s, gpartB[r][1][p1bl][lane]);
                }
                float g0, g1;
                unpack2(s, g0, g1);
                *(float2*)&ghist[j % NS][p1bl][d0] = make_float2(g0, g1);
                x0 += a2.x + g0;
                x1 += a2.y + g1;
            }
            float val = ftanh(x0) * vsm[d0] + ftanh(x1) * vsm[d0 + 1];
            #pragma unroll
            for (int o = 16; o > 0; o >>= 1)
                val += __shfl_down_sync(0xffffffffu, val, o);
            if (lane == 0) {
                #pragma unroll
                for (int r = 0; r < RANKS; r++)
                    stasync_b32(spush[par], ms_base + 8 * sk, r, __float_as_uint(val));
            }
        }

        // ---- warp 0: wait s, softmax ----
        if (warp == 0) {
            int psv = (sk == 0) ? ps0 : (sk == 1) ? ps1 : (sk == 2) ? ps2 : ps3;
            mbar_wait(ms_base + 8 * sk, psv);
            if (sk == 0) ps0 ^= 1; else if (sk == 1) ps1 ^= 1;
            else if (sk == 2) ps2 ^= 1; else ps3 ^= 1;
            if (lane == 0)
                mbar_arrive_expect(ms_base + 8 * sk, TX_S);   // re-arm for t+4
            if (lane < BPC * NS) {
                const int bl = lane / NS, i = lane - bl * NS;
                float4 u0 = *(float4*)&spart[par][bl][i][0];
                float4 u1 = *(float4*)&spart[par][bl][i][4];
                ssm[lane] = (u0.x + u0.y + u0.z + u0.w) + (u1.x + u1.y + u1.z + u1.w);
            }
            __syncwarp();
            if (lane < BPC) {
                float s[NS];
                #pragma unroll
                for (int i = 0; i < NS; i++) s[i] = ssm[lane * NS + i];
                float m = s[0];
                #pragma unroll
                for (int i = 1; i < NS; i++) m = fmaxf(m, s[i]);
                float e[NS], sum = 0.f;
                #pragma unroll
                for (int i = 0; i < NS; i++) { e[i] = __expf(s[i] - m); sum += e[i]; }
                float inv = __fdividef(1.f, sum);
                #pragma unroll
                for (int i = 0; i < NS; i++) wsm[lane][i] = e[i] * inv;
            }
        }

        // ---- loader warps: deposit t+1, issue LDG t+2 ----
        if (warp >= 10) {
            if (pfrow >= 0) {
                if (pfrow < 10) *(float4*)&pbufA[par ^ 1][pfrow][lq]      = pvA;
                else            *(float4*)&pbufC[par ^ 1][pfrow - 10][lq] = pvA;
            }
            if (pfH) *(float4*)&hbuf[par ^ 1][lbl][lq] = pvH;
            pfrow = -1; pfH = false;
            const int tload = t + 2;
            if (tload < S) {
                if (lrow < 10) {
                    int jbl = lrow / NS, ji = lrow % NS, j = tload - NS + ji;
                    if (j >= 0) {
                        pvA = __ldcs((const float4*)&g_A[((size_t)(b0 + jbl) * S + j) * D + col0 + lq]);
                        pfrow = lrow;
                    }
                } else {
                    pvA = __ldcs((const float4*)&g_C[((size_t)(b0 + lrow - 10) * S + tload) * D + col0 + lq]);
                    pfrow = lrow;
                }
                if (lidx < 32) {
                    pvH = *(const float4*)&Hm[((size_t)(b0 + lbl) * S + tload) * D + col0 + lq];
                    pfH = true;
                }
            }
        }
        __syncthreads();

        // ---- htilde (own cols) ----
        if (tid < BPC * COLS) {
            const int bl = tid >> 6, dd = tid & 63;
            float hh = 0.f;
            #pragma unroll
            for (int i = 0; i < NS; i++) {
                int j = t - NS + i;
                if (j >= 0) hh += wsm[bl][i] * thist[j % NS][bl][dd];
            }
            float hv = hbuf[par][bl][dd] + fmaxf(hh, 0.f);
            thist[t % NS][bl][dd] = hv;
            hdup[bl][dd] = make_float2(hv, hv);
            __stcs(&out[((size_t)(b0 + bl) * S + t) * D + col0 + dd], hv);
        }
        __syncthreads();

        if (t < S - 1) {
            // ---- P3: partial g over k-half, 2 cols x 2 batches ----
            uint64_t acc0 = 0ull, acc1 = 0ull;
            #pragma unroll
            for (int kk = 0; kk < 32; kk++) {
                const int k = khalf * 32 + kk;
                acc0 = fma2(*(uint64_t*)&hdup[0][k], w3p[kk], acc0);
                acc1 = fma2(*(uint64_t*)&hdup[1][k], w3p[kk], acc1);
            }
            // plain remote data stores + one release-arrive per warp
            stc_b64_pre(grd0, acc0);
            stc_b64_pre(grd1, acc1);
            __syncwarp();
            if (lane == 0) arrive_remote(grm[par]);

            // ---- P1-pre for t+1 (i<4 warps) ----
            if (warp < 10 && p1i != NS - 1) {
                float2 c2 = *(float2*)&pbufC[par ^ 1][p1bl][d0];
                float x0 = c2.x, x1 = c2.y;
                const int j = (t + 1) - NS + p1i;
                if (j >= 0) {
                    float2 a2 = *(float2*)&pbufA[par ^ 1][warp][d0];
                    float2 g2 = *(float2*)&ghist[j % NS][p1bl][d0];
                    x0 += a2.x + g2.x;
                    x1 += a2.y + g2.y;
                }
                float val = ftanh(x0) * vsm[d0] + ftanh(x1) * vsm[d0 + 1];
                #pragma unroll
                for (int o = 16; o > 0; o >>= 1)
                    val += __shfl_down_sync(0xffffffffu, val, o);
                if (lane == 0) {
                    #pragma unroll
                    for (int r = 0; r < RANKS; r++)
                        stasync_b32(spush[par ^ 1], ms_base + 8 * ((t + 1) & 3), r,
                                    __float_as_uint(val));
                }
            }
        }
    }

    // Terminal cluster sync: no CTA exits while peers' remote stores could
    // still target its SMEM / mbarriers.
    cluster_sync();
}

// ============================================================
// Launch
// ============================================================
extern "C" void kernel_launch(void* const* d_in, const int* in_sizes, int n_in,
                              void* d_out, int out_size)
{
    (void)in_sizes; (void)n_in; (void)out_size;
    const float* H  = (const float*)d_in[0];
    const float* v  = (const float*)d_in[1];
    const float* W1 = (const float*)d_in[2];
    const float* W2 = (const float*)d_in[3];
    const float* W3 = (const float*)d_in[4];
    float* out = (float*)d_out;

    precompute_kernel<<<dim3((B * S) / PM, 8), 256>>>(H, W1, W2);
    recurrent_kernel<<<NCLUSTERS * RANKS, RTHREADS>>>(H, v, W3, out);
}

// round 10
// speedup vs baseline: 1.0566x; 1.0566x over previous
#include <cuda_runtime.h>
#include <cstdint>

#define DEV_INLINE __device__ __forceinline__

// Problem constants
constexpr int B  = 32;
constexpr int S  = 512;
constexpr int D  = 512;
constexpr int NS = 5;

// Recurrent kernel tiling
constexpr int RANKS     = 8;            // CTAs per cluster
constexpr int BPC       = 2;            // batches per cluster
constexpr int NCLUSTERS = B / BPC;      // 16
constexpr int COLS      = D / RANKS;    // 64 columns per CTA
constexpr int RTHREADS  = 512;

// mbarrier tx budgets (bytes)
constexpr uint32_t TX_G = 4096;  // 8 src * 64 combined b64 pushes
constexpr uint32_t TX_S = 320;   // (64 pre + 16 critical) * 4B

// Scratch (static device arrays; no allocations allowed)
__device__ float g_A[(size_t)B * S * D];       // H @ W1
__device__ float g_C[(size_t)B * S * D];       // H @ W2

// ---------- helpers ----------
DEV_INLINE uint64_t pack2(float lo, float hi) {
    uint64_t r; asm("mov.b64 %0, {%1, %2};" : "=l"(r) : "f"(lo), "f"(hi)); return r;
}
DEV_INLINE void unpack2(uint64_t v, float& lo, float& hi) {
    asm("mov.b64 {%0, %1}, %2;" : "=f"(lo), "=f"(hi) : "l"(v));
}
DEV_INLINE uint64_t fma2(uint64_t a, uint64_t b, uint64_t c) {
    uint64_t d; asm("fma.rn.f32x2 %0, %1, %2, %3;" : "=l"(d) : "l"(a), "l"(b), "l"(c));
    return d;
}
DEV_INLINE uint64_t add2(uint64_t a, uint64_t b) {
    uint64_t d; asm("add.rn.f32x2 %0, %1, %2;" : "=l"(d) : "l"(a), "l"(b));
    return d;
}
// fold khalf pairs: a += shfl_xor(a, 1) on both packed floats
DEV_INLINE uint64_t shflxor1_add2(uint64_t a) {
    float f0, f1;
    unpack2(a, f0, f1);
    float g0 = __shfl_xor_sync(0xffffffffu, f0, 1);
    float g1 = __shfl_xor_sync(0xffffffffu, f1, 1);
    return add2(a, pack2(g0, g1));
}
DEV_INLINE uint32_t su32(const void* p) {
    uint32_t a;
    asm("{ .reg .u64 t; cvta.to.shared.u64 t, %1; cvt.u32.u64 %0, t; }" : "=r"(a) : "l"(p));
    return a;
}
DEV_INLINE uint32_t mapa_u32(uint32_t a, int rank) {
    uint32_t r; asm("mapa.shared::cluster.u32 %0, %1, %2;" : "=r"(r) : "r"(a), "r"(rank));
    return r;
}
// Remote store with mbarrier tx-completion (data+mbar in SAME target CTA)
DEV_INLINE void stasync_b32(uint32_t daddr, uint32_t mbar, int rank, uint32_t v) {
    asm volatile(
        "{ .reg .b32 rd, rm;\n\t"
        "mapa.shared::cluster.u32 rd, %0, %2;\n\t"
        "mapa.shared::cluster.u32 rm, %1, %2;\n\t"
        "st.async.shared::cluster.mbarrier::complete_tx::bytes.b32 [rd], %3, [rm]; }"
        :: "r"(daddr), "r"(mbar), "r"(rank), "r"(v) : "memory");
}
DEV_INLINE void stasync_b64_pre(uint32_t rdaddr, uint32_t rmbar, uint64_t v) {
    asm volatile(
        "st.async.shared::cluster.mbarrier::complete_tx::bytes.b64 [%0], %1, [%2];"
        :: "r"(rdaddr), "l"(v), "r"(rmbar) : "memory");
}
DEV_INLINE void mbar_init(uint32_t a, uint32_t cnt) {
    asm volatile("mbarrier.init.shared.b64 [%0], %1;" :: "r"(a), "r"(cnt) : "memory");
}
DEV_INLINE void mbar_arrive_expect(uint32_t a, uint32_t tx) {
    asm volatile("mbarrier.arrive.expect_tx.shared.b64 _, [%0], %1;"
                 :: "r"(a), "r"(tx) : "memory");
}
// CTA-scope acquire: st.async complete_tx fires after data is visible in
// OUR local smem (same contract as TMA complete_tx consumers). R8-proven.
DEV_INLINE void mbar_wait(uint32_t mbar, uint32_t parity) {
    asm volatile(
        "{\n\t"
        ".reg .pred P;\n\t"
        "WAIT_%=:\n\t"
        "mbarrier.try_wait.parity.acquire.cta.shared::cta.b64 P, [%0], %1, 0x989680;\n\t"
        "@P bra.uni DONE_%=;\n\t"
        "bra.uni WAIT_%=;\n\t"
        "DONE_%=:\n\t"
        "}"
        :: "r"(mbar), "r"(parity) : "memory");
}
DEV_INLINE void cluster_sync() {
    asm volatile("barrier.cluster.arrive.aligned;" ::: "memory");
    asm volatile("barrier.cluster.wait.aligned;"   ::: "memory");
}
// fast tanh via __expf, clamped so exp never overflows
DEV_INLINE float ftanh(float x) {
    x = fminf(15.f, fmaxf(-15.f, x));
    float e = __expf(x + x);
    return __fdividef(e - 1.f, e + 1.f);
}

// ============================================================
// Precompute: A = H @ W1, C = H @ W2   (fp32, f32x2 FMAs)
// ============================================================
constexpr int PM = 128, PN = 128, PK = 16;

__global__ __launch_bounds__(256) void precompute_kernel(
    const float* __restrict__ Hm,
    const float* __restrict__ W1,
    const float* __restrict__ W2)
{
    __shared__ float As[PK][PM];
    __shared__ float Bs[PK][PN];

    const int tid   = threadIdx.x;
    const int which = blockIdx.y >> 2;
    const int n0    = (blockIdx.y & 3) * PN;
    const int m0    = blockIdx.x * PM;
    const float* W  = which ? W2 : W1;
    float* OUT      = which ? g_C : g_A;

    const int tx = tid & 15;
    const int ty = tid >> 4;

    uint64_t acc[8][4];
    #pragma unroll
    for (int i = 0; i < 8; i++)
        #pragma unroll
        for (int j = 0; j < 4; j++) acc[i][j] = 0ull;

    for (int kt = 0; kt < 512; kt += PK) {
        #pragma unroll
        for (int i = 0; i < 2; i++) {
            int idx4 = i * 256 + tid;
            int m  = idx4 >> 2;
            int kq = (idx4 & 3) * 4;
            float4 vv = *(const float4*)&Hm[(size_t)(m0 + m) * 512 + kt + kq];
            As[kq + 0][m] = vv.x; As[kq + 1][m] = vv.y;
            As[kq + 2][m] = vv.z; As[kq + 3][m] = vv.w;
        }
        #pragma unroll
        for (int i = 0; i < 2; i++) {
            int idx4 = i * 256 + tid;
            int n4 = (idx4 & 31) * 4;
            int k  = idx4 >> 5;
            *(float4*)&Bs[k][n4] = *(const float4*)&W[(size_t)(kt + k) * 512 + n0 + n4];
        }
        __syncthreads();

        #pragma unroll
        for (int k = 0; k < PK; k++) {
            float4 a0 = *(const float4*)&As[k][ty * 8];
            float4 a1 = *(const float4*)&As[k][ty * 8 + 4];
            float4 b0 = *(const float4*)&Bs[k][tx * 8];
            float4 b1 = *(const float4*)&Bs[k][tx * 8 + 4];
            float av[8] = {a0.x, a0.y, a0.z, a0.w, a1.x, a1.y, a1.z, a1.w};
            uint64_t bp[4];
            bp[0] = pack2(b0.x, b0.y); bp[1] = pack2(b0.z, b0.w);
            bp[2] = pack2(b1.x, b1.y); bp[3] = pack2(b1.z, b1.w);
            #pragma unroll
            for (int i = 0; i < 8; i++) {
                uint64_t ad = pack2(av[i], av[i]);
                #pragma unroll
                for (int j = 0; j < 4; j++)
                    acc[i][j] = fma2(ad, bp[j], acc[i][j]);
            }
        }
        __syncthreads();
    }

    #pragma unroll
    for (int i = 0; i < 8; i++) {
        int row = m0 + ty * 8 + i;
        float f0, f1, f2, f3, f4, f5, f6, f7;
        unpack2(acc[i][0], f0, f1); unpack2(acc[i][1], f2, f3);
        unpack2(acc[i][2], f4, f5); unpack2(acc[i][3], f6, f7);
        *(float4*)&OUT[(size_t)row * 512 + n0 + tx * 8]     = make_float4(f0, f1, f2, f3);
        *(float4*)&OUT[(size_t)row * 512 + n0 + tx * 8 + 4] = make_float4(f4, f5, f6, f7);
    }
}

// ============================================================
// Recurrent kernel: R8 base (st.async g + s, acquire.cta waits).
// ONE change: P3 khalf moved to lane parity; shfl_xor(1) combines
// the two k-halves in-register; even lanes push the combined b64.
// g-exchange volume 8KB -> 4KB/step; consumer sum 16 -> 8 partials.
// ============================================================
__global__ __launch_bounds__(RTHREADS, 1) __cluster_dims__(RANKS, 1, 1)
void recurrent_kernel(const float* __restrict__ Hm,
                      const float* __restrict__ v,
                      const float* __restrict__ W3,
                      float* __restrict__ out)
{
    __shared__ float2   hdup[BPC][COLS];             // (hv,hv) per batch/own col
    __shared__ float    thist[NS][BPC][COLS];        // htilde history
    __shared__ float    ghist[NS][BPC][COLS];        // summed g history
    __shared__ uint64_t gpartB[RANKS][BPC][32];      // [src][bl][pair] combined
    __shared__ float    spart[2][BPC][NS][RANKS];    // logit partials, parity
    __shared__ float    pbufA[2][BPC * NS][COLS];    // prefetched g_A rows
    __shared__ float    pbufC[2][BPC][COLS];         // prefetched g_C rows
    __shared__ float    hbuf[2][BPC][COLS];          // prefetched H rows
    __shared__ float    vsm[COLS];
    __shared__ float    ssm[BPC * NS];
    __shared__ float    wsm[BPC][NS];
    __shared__ uint64_t mbars[6];                    // [0..1]=g ring, [2..5]=s ring

    const int tid  = threadIdx.x;
    const int warp = tid >> 5, lane = tid & 31;
    const int rank = blockIdx.x & (RANKS - 1);
    const int cl   = blockIdx.x >> 3;
    const int col0 = rank * COLS;
    const int b0   = cl * BPC;

    const uint32_t mg_base = su32(&mbars[0]);        // + 8*b  (b = 0,1)
    const uint32_t ms_base = su32(&mbars[2]);        // + 8*k  (k = 0..3)

    // ---- init mbarriers, then cluster-wide visibility ----
    if (tid == 0) {
        #pragma unroll
        for (int i = 0; i < 6; i++) mbar_init(su32(&mbars[i]), 1);
        mbar_arrive_expect(mg_base + 0, TX_G);       // g data t=0
        mbar_arrive_expect(mg_base + 8, TX_G);       // g data t=1
        #pragma unroll
        for (int k = 0; k < 4; k++) mbar_arrive_expect(ms_base + 8 * k, TX_S);
    }
    if (tid < COLS) vsm[tid] = v[col0 + tid];
    for (int i = tid; i < NS * BPC * COLS; i += RTHREADS) {
        ((float*)ghist)[i] = 0.f;
        ((float*)thist)[i] = 0.f;
    }
    __syncthreads();
    cluster_sync();   // all mbarriers initialized before any remote st.async

    // ---- P3 identities: khalf on lane parity, pair on lane>>1 ----
    // pairIdx = warp*16 + (lane>>1) covers 256 col-pairs; gdst = warp>>1
    // (warp-uniform). Even lane pushes the shfl-combined value.
    const int p3pair  = warp * 16 + (lane >> 1);
    const int p3khalf = lane & 1;
    const int gcol    = p3pair * 2;
    const int gdst    = warp >> 1;                   // destination rank
    const uint32_t grd0 = mapa_u32(su32(&gpartB[rank][0][p3pair & 31]), gdst);
    const uint32_t grd1 = mapa_u32(su32(&gpartB[rank][1][p3pair & 31]), gdst);
    uint32_t grm[2];
    grm[0] = mapa_u32(mg_base + 0, gdst);
    grm[1] = mapa_u32(mg_base + 8, gdst);

    // W3 slice: 32 k-rows (this thread's khalf) x 2 adjacent cols, pair-packed
    uint64_t w3p[32];
    #pragma unroll
    for (int kk = 0; kk < 32; kk++)
        w3p[kk] = *(const uint64_t*)&W3[(size_t)(col0 + p3khalf * 32 + kk) * D + gcol];

    // loader ids (warps 10-15)
    const int lidx = tid - 320;
    const int lrow = lidx >> 4;            // 0..11
    const int lq   = (lidx & 15) * 4;
    const int lbl  = (lidx >> 4) & 1;

    // P1 ids
    const int p1bl = (warp < 10) ? warp / NS : 0;
    const int p1i  = (warp < 10) ? warp % NS : 0;
    const int d0   = lane * 2;
    uint32_t spush[2];
    spush[0] = su32(&spart[0][p1bl][p1i][rank]);
    spush[1] = su32(&spart[1][p1bl][p1i][rank]);

    // mbarrier phase parities
    int pg0 = 0, pg1 = 0;
    int ps0 = 0, ps1 = 0, ps2 = 0, ps3 = 0;

    // ---- prologue: load t=0 C/H rows ----
    if (warp >= 10) {
        if (lrow >= 10)
            *(float4*)&pbufC[0][lrow - 10][lq] =
                __ldcs((const float4*)&g_C[((size_t)(b0 + lrow - 10) * S + 0) * D + col0 + lq]);
        if (lidx < 32)
            *(float4*)&hbuf[0][lbl][lq] =
                *(const float4*)&Hm[((size_t)(b0 + lbl) * S + 0) * D + col0 + lq];
    }
    __syncthreads();

    // prologue P1-pre for t=0 (i<4 warps; all j<0 -> c-only)
    if (warp < 10 && p1i != NS - 1) {
        float2 c2 = *(float2*)&pbufC[0][p1bl][d0];
        float val = ftanh(c2.x) * vsm[d0] + ftanh(c2.y) * vsm[d0 + 1];
        #pragma unroll
        for (int o = 16; o > 0; o >>= 1)
            val += __shfl_down_sync(0xffffffffu, val, o);
        if (lane == 0) {
            #pragma unroll
            for (int r = 0; r < RANKS; r++)
                stasync_b32(spush[0], ms_base + 0, r, __float_as_uint(val));
        }
    }

    // prologue: issue LDGs for t=1
    float4 pvA = make_float4(0.f, 0.f, 0.f, 0.f);
    float4 pvH = make_float4(0.f, 0.f, 0.f, 0.f);
    int pfrow = -1; bool pfH = false;
    if (warp >= 10) {
        if (lrow < 10) {
            int jbl = lrow / NS, ji = lrow % NS, j = 1 - NS + ji;
            if (j >= 0) {
                pvA = __ldcs((const float4*)&g_A[((size_t)(b0 + jbl) * S + j) * D + col0 + lq]);
                pfrow = lrow;
            }
        } else {
            pvA = __ldcs((const float4*)&g_C[((size_t)(b0 + lrow - 10) * S + 1) * D + col0 + lq]);
            pfrow = lrow;
        }
        if (lidx < 32) {
            pvH = *(const float4*)&Hm[((size_t)(b0 + lbl) * S + 1) * D + col0 + lq];
            pfH = true;
        }
    }

    for (int t = 0; t < S; t++) {
        const int par = t & 1;
        const int sk  = t & 3;

        // ---- critical warps (4, 9): wait g(t-1), sum, logit, push s ----
        if (warp < 10 && p1i == NS - 1) {
            const int j = t - 1;
            if (j >= 0) {
                const int gb = j & 1;
                mbar_wait(mg_base + 8 * gb, gb ? pg1 : pg0);
                if (gb) pg1 ^= 1; else pg0 ^= 1;
                if (warp == 4 && lane == 0)   // re-arm for data t+1
                    mbar_arrive_expect(mg_base + 8 * gb, TX_G);
            }
            float2 c2 = *(float2*)&pbufC[par][p1bl][d0];
            float x0 = c2.x, x1 = c2.y;
            if (j >= 0) {
                float2 a2 = *(float2*)&pbufA[par][warp][d0];
                uint64_t s = 0ull;
                #pragma unroll
                for (int r = 0; r < RANKS; r++)
                    s = add2(s, gpartB[r][p1bl][lane]);
                float g0, g1;
                unpack2(s, g0, g1);
                *(float2*)&ghist[j % NS][p1bl][d0] = make_float2(g0, g1);
                x0 += a2.x + g0;
                x1 += a2.y + g1;
            }
            float val = ftanh(x0) * vsm[d0] + ftanh(x1) * vsm[d0 + 1];
            #pragma unroll
            for (int o = 16; o > 0; o >>= 1)
                val += __shfl_down_sync(0xffffffffu, val, o);
            if (lane == 0) {
                #pragma unroll
                for (int r = 0; r < RANKS; r++)
                    stasync_b32(spush[par], ms_base + 8 * sk, r, __float_as_uint(val));
            }
        }

        // ---- warp 0: wait s, softmax ----
        if (warp == 0) {
            int psv = (sk == 0) ? ps0 : (sk == 1) ? ps1 : (sk == 2) ? ps2 : ps3;
            mbar_wait(ms_base + 8 * sk, psv);
            if (sk == 0) ps0 ^= 1; else if (sk == 1) ps1 ^= 1;
            else if (sk == 2) ps2 ^= 1; else ps3 ^= 1;
            if (lane == 0)
                mbar_arrive_expect(ms_base + 8 * sk, TX_S);   // re-arm for t+4
            if (lane < BPC * NS) {
                const int bl = lane / NS, i = lane - bl * NS;
                float4 u0 = *(float4*)&spart[par][bl][i][0];
                float4 u1 = *(float4*)&spart[par][bl][i][4];
                ssm[lane] = (u0.x + u0.y + u0.z + u0.w) + (u1.x + u1.y + u1.z + u1.w);
            }
            __syncwarp();
            if (lane < BPC) {
                float s[NS];
                #pragma unroll
                for (int i = 0; i < NS; i++) s[i] = ssm[lane * NS + i];
                float m = s[0];
                #pragma unroll
                for (int i = 1; i < NS; i++) m = fmaxf(m, s[i]);
                float e[NS], sum = 0.f;
                #pragma unroll
                for (int i = 0; i < NS; i++) { e[i] = __expf(s[i] - m); sum += e[i]; }
                float inv = __fdividef(1.f, sum);
                #pragma unroll
                for (int i = 0; i < NS; i++) wsm[lane][i] = e[i] * inv;
            }
        }

        // ---- loader warps: deposit t+1, issue LDG t+2 ----
        if (warp >= 10) {
            if (pfrow >= 0) {
                if (pfrow < 10) *(float4*)&pbufA[par ^ 1][pfrow][lq]      = pvA;
                else            *(float4*)&pbufC[par ^ 1][pfrow - 10][lq] = pvA;
            }
            if (pfH) *(float4*)&hbuf[par ^ 1][lbl][lq] = pvH;
            pfrow = -1; pfH = false;
            const int tload = t + 2;
            if (tload < S) {
                if (lrow < 10) {
                    int jbl = lrow / NS, ji = lrow % NS, j = tload - NS + ji;
                    if (j >= 0) {
                        pvA = __ldcs((const float4*)&g_A[((size_t)(b0 + jbl) * S + j) * D + col0 + lq]);
                        pfrow = lrow;
                    }
                } else {
                    pvA = __ldcs((const float4*)&g_C[((size_t)(b0 + lrow - 10) * S + tload) * D + col0 + lq]);
                    pfrow = lrow;
                }
                if (lidx < 32) {
                    pvH = *(const float4*)&Hm[((size_t)(b0 + lbl) * S + tload) * D + col0 + lq];
                    pfH = true;
                }
            }
        }
        __syncthreads();

        // ---- htilde (own cols) ----
        if (tid < BPC * COLS) {
            const int bl = tid >> 6, dd = tid & 63;
            float hh = 0.f;
            #pragma unroll
            for (int i = 0; i < NS; i++) {
                int j = t - NS + i;
                if (j >= 0) hh += wsm[bl][i] * thist[j % NS][bl][dd];
            }
            float hv = hbuf[par][bl][dd] + fmaxf(hh, 0.f);
            thist[t % NS][bl][dd] = hv;
            hdup[bl][dd] = make_float2(hv, hv);
            __stcs(&out[((size_t)(b0 + bl) * S + t) * D + col0 + dd], hv);
        }
        __syncthreads();

        if (t < S - 1) {
            // ---- P3: partial g over this thread's khalf, 2 cols x 2 batches ----
            uint64_t acc0 = 0ull, acc1 = 0ull;
            #pragma unroll
            for (int kk = 0; kk < 32; kk++) {
                const int k = p3khalf * 32 + kk;
                acc0 = fma2(*(uint64_t*)&hdup[0][k], w3p[kk], acc0);
                acc1 = fma2(*(uint64_t*)&hdup[1][k], w3p[kk], acc1);
            }
            // fold the two k-halves across lane parity, push once per pair
            acc0 = shflxor1_add2(acc0);
            acc1 = shflxor1_add2(acc1);
            if (p3khalf == 0) {
                stasync_b64_pre(grd0, grm[par], acc0);
                stasync_b64_pre(grd1, grm[par], acc1);
            }

            // ---- P1-pre for t+1 (i<4 warps) ----
            if (warp < 10 && p1i != NS - 1) {
                float2 c2 = *(float2*)&pbufC[par ^ 1][p1bl][d0];
                float x0 = c2.x, x1 = c2.y;
                const int j = (t + 1) - NS + p1i;
                if (j >= 0) {
                    float2 a2 = *(float2*)&pbufA[par ^ 1][warp][d0];
                    float2 g2 = *(float2*)&ghist[j % NS][p1bl][d0];
                    x0 += a2.x + g2.x;
                    x1 += a2.y + g2.y;
                }
                float val = ftanh(x0) * vsm[d0] + ftanh(x1) * vsm[d0 + 1];
                #pragma unroll
                for (int o = 16; o > 0; o >>= 1)
                    val += __shfl_down_sync(0xffffffffu, val, o);
                if (lane == 0) {
                    #pragma unroll
                    for (int r = 0; r < RANKS; r++)
                        stasync_b32(spush[par ^ 1], ms_base + 8 * ((t + 1) & 3), r,
                                    __float_as_uint(val));
                }
            }
        }
    }

    // Terminal cluster sync: no CTA exits while peers' remote stores could
    // still target its SMEM / mbarriers.
    cluster_sync();
}

// ============================================================
// Launch
// ============================================================
extern "C" void kernel_launch(void* const* d_in, const int* in_sizes, int n_in,
                              void* d_out, int out_size)
{
    (void)in_sizes; (void)n_in; (void)out_size;
    const float* H  = (const float*)d_in[0];
    const float* v  = (const float*)d_in[1];
    const float* W1 = (const float*)d_in[2];
    const float* W2 = (const float*)d_in[3];
    const float* W3 = (const float*)d_in[4];
    float* out = (float*)d_out;

    precompute_kernel<<<dim3((B * S) / PM, 8), 256>>>(H, W1, W2);
    recurrent_kernel<<<NCLUSTERS * RANKS, RTHREADS>>>(H, v, W3, out);
}

// round 11
// speedup vs baseline: 1.2367x; 1.1704x over previous
#include <cuda_runtime.h>
#include <cstdint>

#define DEV_INLINE __device__ __forceinline__

// Problem constants
constexpr int B  = 32;
constexpr int S  = 512;
constexpr int D  = 512;
constexpr int NS = 5;

// Recurrent kernel tiling
constexpr int RANKS     = 8;            // CTAs per cluster
constexpr int BPC       = 2;            // batches per cluster
constexpr int NCLUSTERS = B / BPC;      // 16
constexpr int COLS      = D / RANKS;    // 64 columns per CTA
constexpr int RTHREADS  = 512;

// mbarrier tx budgets (bytes)
constexpr uint32_t TX_G = 8192;  // 512 thr * 2 * 8B from 8 src ranks total
constexpr uint32_t TX_S = 320;   // (64 pre + 16 critical) * 4B

// Scratch (static device arrays; no allocations allowed)
__device__ float g_A[(size_t)B * S * D];       // H @ W1
__device__ float g_C[(size_t)B * S * D];       // H @ W2

// ---------- helpers ----------
DEV_INLINE uint64_t pack2(float lo, float hi) {
    uint64_t r; asm("mov.b64 %0, {%1, %2};" : "=l"(r) : "f"(lo), "f"(hi)); return r;
}
DEV_INLINE void unpack2(uint64_t v, float& lo, float& hi) {
    asm("mov.b64 {%0, %1}, %2;" : "=f"(lo), "=f"(hi) : "l"(v));
}
DEV_INLINE uint64_t fma2(uint64_t a, uint64_t b, uint64_t c) {
    uint64_t d; asm("fma.rn.f32x2 %0, %1, %2, %3;" : "=l"(d) : "l"(a), "l"(b), "l"(c));
    return d;
}
DEV_INLINE uint64_t add2(uint64_t a, uint64_t b) {
    uint64_t d; asm("add.rn.f32x2 %0, %1, %2;" : "=l"(d) : "l"(a), "l"(b));
    return d;
}
DEV_INLINE uint32_t su32(const void* p) {
    uint32_t a;
    asm("{ .reg .u64 t; cvta.to.shared.u64 t, %1; cvt.u32.u64 %0, t; }" : "=r"(a) : "l"(p));
    return a;
}
DEV_INLINE uint32_t mapa_u32(uint32_t a, int rank) {
    uint32_t r; asm("mapa.shared::cluster.u32 %0, %1, %2;" : "=r"(r) : "r"(a), "r"(rank));
    return r;
}
// Remote store with mbarrier tx-completion (data+mbar in SAME target CTA)
DEV_INLINE void stasync_b32(uint32_t daddr, uint32_t mbar, int rank, uint32_t v) {
    asm volatile(
        "{ .reg .b32 rd, rm;\n\t"
        "mapa.shared::cluster.u32 rd, %0, %2;\n\t"
        "mapa.shared::cluster.u32 rm, %1, %2;\n\t"
        "st.async.shared::cluster.mbarrier::complete_tx::bytes.b32 [rd], %3, [rm]; }"
        :: "r"(daddr), "r"(mbar), "r"(rank), "r"(v) : "memory");
}
DEV_INLINE void stasync_b64_pre(uint32_t rdaddr, uint32_t rmbar, uint64_t v) {
    asm volatile(
        "st.async.shared::cluster.mbarrier::complete_tx::bytes.b64 [%0], %1, [%2];"
        :: "r"(rdaddr), "l"(v), "r"(rmbar) : "memory");
}
DEV_INLINE void mbar_init(uint32_t a, uint32_t cnt) {
    asm volatile("mbarrier.init.shared.b64 [%0], %1;" :: "r"(a), "r"(cnt) : "memory");
}
DEV_INLINE void mbar_arrive_expect(uint32_t a, uint32_t tx) {
    asm volatile("mbarrier.arrive.expect_tx.shared.b64 _, [%0], %1;"
                 :: "r"(a), "r"(tx) : "memory");
}
// CTA-scope acquire: st.async complete_tx fires after data is visible in
// OUR local smem (same contract as TMA complete_tx consumers). R8-proven.
DEV_INLINE void mbar_wait(uint32_t mbar, uint32_t parity) {
    asm volatile(
        "{\n\t"
        ".reg .pred P;\n\t"
        "WAIT_%=:\n\t"
        "mbarrier.try_wait.parity.acquire.cta.shared::cta.b64 P, [%0], %1, 0x989680;\n\t"
        "@P bra.uni DONE_%=;\n\t"
        "bra.uni WAIT_%=;\n\t"
        "DONE_%=:\n\t"
        "}"
        :: "r"(mbar), "r"(parity) : "memory");
}
DEV_INLINE void cluster_sync() {
    asm volatile("barrier.cluster.arrive.aligned;" ::: "memory");
    asm volatile("barrier.cluster.wait.aligned;"   ::: "memory");
}
// fast tanh via __expf, clamped so exp never overflows
DEV_INLINE float ftanh(float x) {
    x = fminf(15.f, fmaxf(-15.f, x));
    float e = __expf(x + x);
    return __fdividef(e - 1.f, e + 1.f);
}

// ============================================================
// Precompute: A = H @ W1, C = H @ W2   (fp32, f32x2 FMAs)
// ============================================================
constexpr int PM = 128, PN = 128, PK = 16;

__global__ __launch_bounds__(256) void precompute_kernel(
    const float* __restrict__ Hm,
    const float* __restrict__ W1,
    const float* __restrict__ W2)
{
    __shared__ float As[PK][PM];
    __shared__ float Bs[PK][PN];

    const int tid   = threadIdx.x;
    const int which = blockIdx.y >> 2;
    const int n0    = (blockIdx.y & 3) * PN;
    const int m0    = blockIdx.x * PM;
    const float* W  = which ? W2 : W1;
    float* OUT      = which ? g_C : g_A;

    const int tx = tid & 15;
    const int ty = tid >> 4;

    uint64_t acc[8][4];
    #pragma unroll
    for (int i = 0; i < 8; i++)
        #pragma unroll
        for (int j = 0; j < 4; j++) acc[i][j] = 0ull;

    for (int kt = 0; kt < 512; kt += PK) {
        #pragma unroll
        for (int i = 0; i < 2; i++) {
            int idx4 = i * 256 + tid;
            int m  = idx4 >> 2;
            int kq = (idx4 & 3) * 4;
            float4 vv = *(const float4*)&Hm[(size_t)(m0 + m) * 512 + kt + kq];
            As[kq + 0][m] = vv.x; As[kq + 1][m] = vv.y;
            As[kq + 2][m] = vv.z; As[kq + 3][m] = vv.w;
        }
        #pragma unroll
        for (int i = 0; i < 2; i++) {
            int idx4 = i * 256 + tid;
            int n4 = (idx4 & 31) * 4;
            int k  = idx4 >> 5;
            *(float4*)&Bs[k][n4] = *(const float4*)&W[(size_t)(kt + k) * 512 + n0 + n4];
        }
        __syncthreads();

        #pragma unroll
        for (int k = 0; k < PK; k++) {
            float4 a0 = *(const float4*)&As[k][ty * 8];
            float4 a1 = *(const float4*)&As[k][ty * 8 + 4];
            float4 b0 = *(const float4*)&Bs[k][tx * 8];
            float4 b1 = *(const float4*)&Bs[k][tx * 8 + 4];
            float av[8] = {a0.x, a0.y, a0.z, a0.w, a1.x, a1.y, a1.z, a1.w};
            uint64_t bp[4];
            bp[0] = pack2(b0.x, b0.y); bp[1] = pack2(b0.z, b0.w);
            bp[2] = pack2(b1.x, b1.y); bp[3] = pack2(b1.z, b1.w);
            #pragma unroll
            for (int i = 0; i < 8; i++) {
                uint64_t ad = pack2(av[i], av[i]);
                #pragma unroll
                for (int j = 0; j < 4; j++)
                    acc[i][j] = fma2(ad, bp[j], acc[i][j]);
            }
        }
        __syncthreads();
    }

    #pragma unroll
    for (int i = 0; i < 8; i++) {
        int row = m0 + ty * 8 + i;
        float f0, f1, f2, f3, f4, f5, f6, f7;
        unpack2(acc[i][0], f0, f1); unpack2(acc[i][1], f2, f3);
        unpack2(acc[i][2], f4, f5); unpack2(acc[i][3], f6, f7);
        *(float4*)&OUT[(size_t)row * 512 + n0 + tx * 8]     = make_float4(f0, f1, f2, f3);
        *(float4*)&OUT[(size_t)row * 512 + n0 + tx * 8 + 4] = make_float4(f4, f5, f6, f7);
    }
}

// ============================================================
// Recurrent kernel: R8 base (best: 1.80ms). ONE change:
// P3 h-operand layout hdup[BPC][COLS] (2x LDS.64 per k) ->
// hts4[COLS] = (h0,h0,h1,h1) float4 (1x LDS.128 broadcast per k),
// plain C++ loads so the compiler can pipeline them.
// ============================================================
__global__ __launch_bounds__(RTHREADS, 1) __cluster_dims__(RANKS, 1, 1)
void recurrent_kernel(const float* __restrict__ Hm,
                      const float* __restrict__ v,
                      const float* __restrict__ W3,
                      float* __restrict__ out)
{
    __shared__ float4   hts4[COLS];                  // (h0,h0,h1,h1) per own col
    __shared__ float    thist[NS][BPC][COLS];        // htilde history
    __shared__ float    ghist[NS][BPC][COLS];        // summed g history
    __shared__ uint64_t gpartB[RANKS][2][BPC][32];   // [src][khalf][bl][pair]
    __shared__ float    spart[2][BPC][NS][RANKS];    // logit partials, parity
    __shared__ float    pbufA[2][BPC * NS][COLS];    // prefetched g_A rows
    __shared__ float    pbufC[2][BPC][COLS];         // prefetched g_C rows
    __shared__ float    hbuf[2][BPC][COLS];          // prefetched H rows
    __shared__ float    vsm[COLS];
    __shared__ float    ssm[BPC * NS];
    __shared__ float    wsm[BPC][NS];
    __shared__ uint64_t mbars[6];                    // [0..1]=g ring, [2..5]=s ring

    const int tid  = threadIdx.x;
    const int warp = tid >> 5, lane = tid & 31;
    const int rank = blockIdx.x & (RANKS - 1);
    const int cl   = blockIdx.x >> 3;
    const int col0 = rank * COLS;
    const int b0   = cl * BPC;

    const uint32_t mg_base = su32(&mbars[0]);        // + 8*b  (b = 0,1)
    const uint32_t ms_base = su32(&mbars[2]);        // + 8*k  (k = 0..3)

    // ---- init mbarriers, then cluster-wide visibility ----
    if (tid == 0) {
        #pragma unroll
        for (int i = 0; i < 6; i++) mbar_init(su32(&mbars[i]), 1);
        mbar_arrive_expect(mg_base + 0, TX_G);       // g data t=0
        mbar_arrive_expect(mg_base + 8, TX_G);       // g data t=1
        #pragma unroll
        for (int k = 0; k < 4; k++) mbar_arrive_expect(ms_base + 8 * k, TX_S);
    }
    if (tid < COLS) vsm[tid] = v[col0 + tid];
    for (int i = tid; i < NS * BPC * COLS; i += RTHREADS) {
        ((float*)ghist)[i] = 0.f;
        ((float*)thist)[i] = 0.f;
    }
    __syncthreads();
    cluster_sync();   // all mbarriers initialized before any remote st.async

    // ---- P3 identities: thread owns col pair (2p, 2p+1), k-half ----
    const int pairIdx = tid & 255;
    const int khalf   = tid >> 8;
    const int gcol    = pairIdx * 2;
    const int gdst    = pairIdx >> 5;                // destination rank
    const uint32_t grd0 = mapa_u32(su32(&gpartB[rank][khalf][0][pairIdx & 31]), gdst);
    const uint32_t grd1 = mapa_u32(su32(&gpartB[rank][khalf][1][pairIdx & 31]), gdst);
    uint32_t grm[2];
    grm[0] = mapa_u32(mg_base + 0, gdst);
    grm[1] = mapa_u32(mg_base + 8, gdst);

    // W3 slice: 32 k-rows x 2 adjacent cols, pair-packed
    uint64_t w3p[32];
    #pragma unroll
    for (int kk = 0; kk < 32; kk++)
        w3p[kk] = *(const uint64_t*)&W3[(size_t)(col0 + khalf * 32 + kk) * D + gcol];

    // loader ids (warps 10-15)
    const int lidx = tid - 320;
    const int lrow = lidx >> 4;            // 0..11
    const int lq   = (lidx & 15) * 4;
    const int lbl  = (lidx >> 4) & 1;

    // P1 ids
    const int p1bl = (warp < 10) ? warp / NS : 0;
    const int p1i  = (warp < 10) ? warp % NS : 0;
    const int d0   = lane * 2;
    uint32_t spush[2];
    spush[0] = su32(&spart[0][p1bl][p1i][rank]);
    spush[1] = su32(&spart[1][p1bl][p1i][rank]);

    // mbarrier phase parities
    int pg0 = 0, pg1 = 0;
    int ps0 = 0, ps1 = 0, ps2 = 0, ps3 = 0;

    // ---- prologue: load t=0 C/H rows ----
    if (warp >= 10) {
        if (lrow >= 10)
            *(float4*)&pbufC[0][lrow - 10][lq] =
                __ldcs((const float4*)&g_C[((size_t)(b0 + lrow - 10) * S + 0) * D + col0 + lq]);
        if (lidx < 32)
            *(float4*)&hbuf[0][lbl][lq] =
                *(const float4*)&Hm[((size_t)(b0 + lbl) * S + 0) * D + col0 + lq];
    }
    __syncthreads();

    // prologue P1-pre for t=0 (i<4 warps; all j<0 -> c-only)
    if (warp < 10 && p1i != NS - 1) {
        float2 c2 = *(float2*)&pbufC[0][p1bl][d0];
        float val = ftanh(c2.x) * vsm[d0] + ftanh(c2.y) * vsm[d0 + 1];
        #pragma unroll
        for (int o = 16; o > 0; o >>= 1)
            val += __shfl_down_sync(0xffffffffu, val, o);
        if (lane == 0) {
            #pragma unroll
            for (int r = 0; r < RANKS; r++)
                stasync_b32(spush[0], ms_base + 0, r, __float_as_uint(val));
        }
    }

    // prologue: issue LDGs for t=1
    float4 pvA = make_float4(0.f, 0.f, 0.f, 0.f);
    float4 pvH = make_float4(0.f, 0.f, 0.f, 0.f);
    int pfrow = -1; bool pfH = false;
    if (warp >= 10) {
        if (lrow < 10) {
            int jbl = lrow / NS, ji = lrow % NS, j = 1 - NS + ji;
            if (j >= 0) {
                pvA = __ldcs((const float4*)&g_A[((size_t)(b0 + jbl) * S + j) * D + col0 + lq]);
                pfrow = lrow;
            }
        } else {
            pvA = __ldcs((const float4*)&g_C[((size_t)(b0 + lrow - 10) * S + 1) * D + col0 + lq]);
            pfrow = lrow;
        }
        if (lidx < 32) {
            pvH = *(const float4*)&Hm[((size_t)(b0 + lbl) * S + 1) * D + col0 + lq];
            pfH = true;
        }
    }

    for (int t = 0; t < S; t++) {
        const int par = t & 1;
        const int sk  = t & 3;

        // ---- critical warps (4, 9): wait g(t-1), sum, logit, push s ----
        if (warp < 10 && p1i == NS - 1) {
            const int j = t - 1;
            if (j >= 0) {
                const int gb = j & 1;
                mbar_wait(mg_base + 8 * gb, gb ? pg1 : pg0);
                if (gb) pg1 ^= 1; else pg0 ^= 1;
                if (warp == 4 && lane == 0)   // re-arm for data t+1
                    mbar_arrive_expect(mg_base + 8 * gb, TX_G);
            }
            float2 c2 = *(float2*)&pbufC[par][p1bl][d0];
            float x0 = c2.x, x1 = c2.y;
            if (j >= 0) {
                float2 a2 = *(float2*)&pbufA[par][warp][d0];
                uint64_t s = 0ull;
                #pragma unroll
                for (int r = 0; r < RANKS; r++) {
                    s = add2(s, gpartB[r][0][p1bl][lane]);
                    s = add2(s, gpartB[r][1][p1bl][lane]);
                }
                float g0, g1;
                unpack2(s, g0, g1);
                *(float2*)&ghist[j % NS][p1bl][d0] = make_float2(g0, g1);
                x0 += a2.x + g0;
                x1 += a2.y + g1;
            }
            float val = ftanh(x0) * vsm[d0] + ftanh(x1) * vsm[d0 + 1];
            #pragma unroll
            for (int o = 16; o > 0; o >>= 1)
                val += __shfl_down_sync(0xffffffffu, val, o);
            if (lane == 0) {
                #pragma unroll
                for (int r = 0; r < RANKS; r++)
                    stasync_b32(spush[par], ms_base + 8 * sk, r, __float_as_uint(val));
            }
        }

        // ---- warp 0: wait s, softmax ----
        if (warp == 0) {
            int psv = (sk == 0) ? ps0 : (sk == 1) ? ps1 : (sk == 2) ? ps2 : ps3;
            mbar_wait(ms_base + 8 * sk, psv);
            if (sk == 0) ps0 ^= 1; else if (sk == 1) ps1 ^= 1;
            else if (sk == 2) ps2 ^= 1; else ps3 ^= 1;
            if (lane == 0)
                mbar_arrive_expect(ms_base + 8 * sk, TX_S);   // re-arm for t+4
            if (lane < BPC * NS) {
                const int bl = lane / NS, i = lane - bl * NS;
                float4 u0 = *(float4*)&spart[par][bl][i][0];
                float4 u1 = *(float4*)&spart[par][bl][i][4];
                ssm[lane] = (u0.x + u0.y + u0.z + u0.w) + (u1.x + u1.y + u1.z + u1.w);
            }
            __syncwarp();
            if (lane < BPC) {
                float s[NS];
                #pragma unroll
                for (int i = 0; i < NS; i++) s[i] = ssm[lane * NS + i];
                float m = s[0];
                #pragma unroll
                for (int i = 1; i < NS; i++) m = fmaxf(m, s[i]);
                float e[NS], sum = 0.f;
                #pragma unroll
                for (int i = 0; i < NS; i++) { e[i] = __expf(s[i] - m); sum += e[i]; }
                float inv = __fdividef(1.f, sum);
                #pragma unroll
                for (int i = 0; i < NS; i++) wsm[lane][i] = e[i] * inv;
            }
        }

        // ---- loader warps: deposit t+1, issue LDG t+2 ----
        if (warp >= 10) {
            if (pfrow >= 0) {
                if (pfrow < 10) *(float4*)&pbufA[par ^ 1][pfrow][lq]      = pvA;
                else            *(float4*)&pbufC[par ^ 1][pfrow - 10][lq] = pvA;
            }
            if (pfH) *(float4*)&hbuf[par ^ 1][lbl][lq] = pvH;
            pfrow = -1; pfH = false;
            const int tload = t + 2;
            if (tload < S) {
                if (lrow < 10) {
                    int jbl = lrow / NS, ji = lrow % NS, j = tload - NS + ji;
                    if (j >= 0) {
                        pvA = __ldcs((const float4*)&g_A[((size_t)(b0 + jbl) * S + j) * D + col0 + lq]);
                        pfrow = lrow;
                    }
                } else {
                    pvA = __ldcs((const float4*)&g_C[((size_t)(b0 + lrow - 10) * S + tload) * D + col0 + lq]);
                    pfrow = lrow;
                }
                if (lidx < 32) {
                    pvH = *(const float4*)&Hm[((size_t)(b0 + lbl) * S + tload) * D + col0 + lq];
                    pfH = true;
                }
            }
        }
        __syncthreads();

        // ---- htilde (own cols) ----
        if (tid < BPC * COLS) {
            const int bl = tid >> 6, dd = tid & 63;
            float hh = 0.f;
            #pragma unroll
            for (int i = 0; i < NS; i++) {
                int j = t - NS + i;
                if (j >= 0) hh += wsm[bl][i] * thist[j % NS][bl][dd];
            }
            float hv = hbuf[par][bl][dd] + fmaxf(hh, 0.f);
            thist[t % NS][bl][dd] = hv;
            *(float2*)((float*)&hts4[dd] + 2 * bl) = make_float2(hv, hv);
            __stcs(&out[((size_t)(b0 + bl) * S + t) * D + col0 + dd], hv);
        }
        __syncthreads();

        if (t < S - 1) {
            // ---- P3: partial g over k-half, 2 cols x 2 batches ----
            // one LDS.128 broadcast per k: (h0,h0,h1,h1)
            uint64_t acc0 = 0ull, acc1 = 0ull;
            #pragma unroll
            for (int kk = 0; kk < 32; kk++) {
                float4 h = hts4[khalf * 32 + kk];
                acc0 = fma2(pack2(h.x, h.y), w3p[kk], acc0);
                acc1 = fma2(pack2(h.z, h.w), w3p[kk], acc1);
            }
            stasync_b64_pre(grd0, grm[par], acc0);
            stasync_b64_pre(grd1, grm[par], acc1);

            // ---- P1-pre for t+1 (i<4 warps) ----
            if (warp < 10 && p1i != NS - 1) {
                float2 c2 = *(float2*)&pbufC[par ^ 1][p1bl][d0];
                float x0 = c2.x, x1 = c2.y;
                const int j = (t + 1) - NS + p1i;
                if (j >= 0) {
                    float2 a2 = *(float2*)&pbufA[par ^ 1][warp][d0];
                    float2 g2 = *(float2*)&ghist[j % NS][p1bl][d0];
                    x0 += a2.x + g2.x;
                    x1 += a2.y + g2.y;
                }
                float val = ftanh(x0) * vsm[d0] + ftanh(x1) * vsm[d0 + 1];
                #pragma unroll
                for (int o = 16; o > 0; o >>= 1)
                    val += __shfl_down_sync(0xffffffffu, val, o);
                if (lane == 0) {
                    #pragma unroll
                    for (int r = 0; r < RANKS; r++)
                        stasync_b32(spush[par ^ 1], ms_base + 8 * ((t + 1) & 3), r,
                                    __float_as_uint(val));
                }
            }
        }
    }

    // Terminal cluster sync: no CTA exits while peers' remote stores could
    // still target its SMEM / mbarriers.
    cluster_sync();
}

// ============================================================
// Launch
// ============================================================
extern "C" void kernel_launch(void* const* d_in, const int* in_sizes, int n_in,
                              void* d_out, int out_size)
{
    (void)in_sizes; (void)n_in; (void)out_size;
    const float* H  = (const float*)d_in[0];
    const float* v  = (const float*)d_in[1];
    const float* W1 = (const float*)d_in[2];
    const float* W2 = (const float*)d_in[3];
    const float* W3 = (const float*)d_in[4];
    float* out = (float*)d_out;

    precompute_kernel<<<dim3((B * S) / PM, 8), 256>>>(H, W1, W2);
    recurrent_kernel<<<NCLUSTERS * RANKS, RTHREADS>>>(H, v, W3, out);
}

// round 12
// speedup vs baseline: 1.3794x; 1.1154x over previous
#include <cuda_runtime.h>
#include <cstdint>

#define DEV_INLINE __device__ __forceinline__

// Problem constants
constexpr int B  = 32;
constexpr int S  = 512;
constexpr int D  = 512;
constexpr int NS = 5;

// Recurrent kernel tiling
constexpr int RANKS     = 8;            // CTAs per cluster
constexpr int BPC       = 2;            // batches per cluster
constexpr int NCLUSTERS = B / BPC;      // 16
constexpr int COLS      = D / RANKS;    // 64 columns per CTA
constexpr int RTHREADS  = 512;

// mbarrier tx budgets (bytes)
constexpr uint32_t TX_G = 8192;  // 512 thr * 2 * 8B from 8 src ranks total
constexpr uint32_t TX_S = 320;   // (64 pre + 16 critical) * 4B

// Scratch (static device arrays; no allocations allowed)
__device__ float g_A[(size_t)B * S * D];       // H @ W1
__device__ float g_C[(size_t)B * S * D];       // H @ W2

// ---------- helpers ----------
DEV_INLINE uint64_t pack2(float lo, float hi) {
    uint64_t r; asm("mov.b64 %0, {%1, %2};" : "=l"(r) : "f"(lo), "f"(hi)); return r;
}
DEV_INLINE void unpack2(uint64_t v, float& lo, float& hi) {
    asm("mov.b64 {%0, %1}, %2;" : "=f"(lo), "=f"(hi) : "l"(v));
}
DEV_INLINE uint64_t fma2(uint64_t a, uint64_t b, uint64_t c) {
    uint64_t d; asm("fma.rn.f32x2 %0, %1, %2, %3;" : "=l"(d) : "l"(a), "l"(b), "l"(c));
    return d;
}
DEV_INLINE uint64_t add2(uint64_t a, uint64_t b) {
    uint64_t d; asm("add.rn.f32x2 %0, %1, %2;" : "=l"(d) : "l"(a), "l"(b));
    return d;
}
DEV_INLINE uint32_t su32(const void* p) {
    uint32_t a;
    asm("{ .reg .u64 t; cvta.to.shared.u64 t, %1; cvt.u32.u64 %0, t; }" : "=r"(a) : "l"(p));
    return a;
}
DEV_INLINE uint32_t mapa_u32(uint32_t a, int rank) {
    uint32_t r; asm("mapa.shared::cluster.u32 %0, %1, %2;" : "=r"(r) : "r"(a), "r"(rank));
    return r;
}
// Remote store with mbarrier tx-completion (data+mbar in SAME target CTA)
DEV_INLINE void stasync_b32(uint32_t daddr, uint32_t mbar, int rank, uint32_t v) {
    asm volatile(
        "{ .reg .b32 rd, rm;\n\t"
        "mapa.shared::cluster.u32 rd, %0, %2;\n\t"
        "mapa.shared::cluster.u32 rm, %1, %2;\n\t"
        "st.async.shared::cluster.mbarrier::complete_tx::bytes.b32 [rd], %3, [rm]; }"
        :: "r"(daddr), "r"(mbar), "r"(rank), "r"(v) : "memory");
}
DEV_INLINE void stasync_b64_pre(uint32_t rdaddr, uint32_t rmbar, uint64_t v) {
    asm volatile(
        "st.async.shared::cluster.mbarrier::complete_tx::bytes.b64 [%0], %1, [%2];"
        :: "r"(rdaddr), "l"(v), "r"(rmbar) : "memory");
}
DEV_INLINE void mbar_init(uint32_t a, uint32_t cnt) {
    asm volatile("mbarrier.init.shared.b64 [%0], %1;" :: "r"(a), "r"(cnt) : "memory");
}
DEV_INLINE void mbar_arrive_expect(uint32_t a, uint32_t tx) {
    asm volatile("mbarrier.arrive.expect_tx.shared.b64 _, [%0], %1;"
                 :: "r"(a), "r"(tx) : "memory");
}
// CTA-scope acquire: st.async complete_tx fires after data is visible in
// OUR local smem (same contract as TMA complete_tx consumers). R8-proven.
DEV_INLINE void mbar_wait(uint32_t mbar, uint32_t parity) {
    asm volatile(
        "{\n\t"
        ".reg .pred P;\n\t"
        "WAIT_%=:\n\t"
        "mbarrier.try_wait.parity.acquire.cta.shared::cta.b64 P, [%0], %1, 0x989680;\n\t"
        "@P bra.uni DONE_%=;\n\t"
        "bra.uni WAIT_%=;\n\t"
        "DONE_%=:\n\t"
        "}"
        :: "r"(mbar), "r"(parity) : "memory");
}
DEV_INLINE void cluster_sync() {
    asm volatile("barrier.cluster.arrive.aligned;" ::: "memory");
    asm volatile("barrier.cluster.wait.aligned;"   ::: "memory");
}
// fast tanh via __expf, clamped so exp never overflows
DEV_INLINE float ftanh(float x) {
    x = fminf(15.f, fmaxf(-15.f, x));
    float e = __expf(x + x);
    return __fdividef(e - 1.f, e + 1.f);
}

// ============================================================
// Precompute: A = H @ W1, C = H @ W2   (fp32, f32x2 FMAs)
// ============================================================
constexpr int PM = 128, PN = 128, PK = 16;

__global__ __launch_bounds__(256) void precompute_kernel(
    const float* __restrict__ Hm,
    const float* __restrict__ W1,
    const float* __restrict__ W2)
{
    __shared__ float As[PK][PM];
    __shared__ float Bs[PK][PN];

    const int tid   = threadIdx.x;
    const int which = blockIdx.y >> 2;
    const int n0    = (blockIdx.y & 3) * PN;
    const int m0    = blockIdx.x * PM;
    const float* W  = which ? W2 : W1;
    float* OUT      = which ? g_C : g_A;

    const int tx = tid & 15;
    const int ty = tid >> 4;

    uint64_t acc[8][4];
    #pragma unroll
    for (int i = 0; i < 8; i++)
        #pragma unroll
        for (int j = 0; j < 4; j++) acc[i][j] = 0ull;

    for (int kt = 0; kt < 512; kt += PK) {
        #pragma unroll
        for (int i = 0; i < 2; i++) {
            int idx4 = i * 256 + tid;
            int m  = idx4 >> 2;
            int kq = (idx4 & 3) * 4;
            float4 vv = *(const float4*)&Hm[(size_t)(m0 + m) * 512 + kt + kq];
            As[kq + 0][m] = vv.x; As[kq + 1][m] = vv.y;
            As[kq + 2][m] = vv.z; As[kq + 3][m] = vv.w;
        }
        #pragma unroll
        for (int i = 0; i < 2; i++) {
            int idx4 = i * 256 + tid;
            int n4 = (idx4 & 31) * 4;
            int k  = idx4 >> 5;
            *(float4*)&Bs[k][n4] = *(const float4*)&W[(size_t)(kt + k) * 512 + n0 + n4];
        }
        __syncthreads();

        #pragma unroll
        for (int k = 0; k < PK; k++) {
            float4 a0 = *(const float4*)&As[k][ty * 8];
            float4 a1 = *(const float4*)&As[k][ty * 8 + 4];
            float4 b0 = *(const float4*)&Bs[k][tx * 8];
            float4 b1 = *(const float4*)&Bs[k][tx * 8 + 4];
            float av[8] = {a0.x, a0.y, a0.z, a0.w, a1.x, a1.y, a1.z, a1.w};
            uint64_t bp[4];
            bp[0] = pack2(b0.x, b0.y); bp[1] = pack2(b0.z, b0.w);
            bp[2] = pack2(b1.x, b1.y); bp[3] = pack2(b1.z, b1.w);
            #pragma unroll
            for (int i = 0; i < 8; i++) {
                uint64_t ad = pack2(av[i], av[i]);
                #pragma unroll
                for (int j = 0; j < 4; j++)
                    acc[i][j] = fma2(ad, bp[j], acc[i][j]);
            }
        }
        __syncthreads();
    }

    #pragma unroll
    for (int i = 0; i < 8; i++) {
        int row = m0 + ty * 8 + i;
        float f0, f1, f2, f3, f4, f5, f6, f7;
        unpack2(acc[i][0], f0, f1); unpack2(acc[i][1], f2, f3);
        unpack2(acc[i][2], f4, f5); unpack2(acc[i][3], f6, f7);
        *(float4*)&OUT[(size_t)row * 512 + n0 + tx * 8]     = make_float4(f0, f1, f2, f3);
        *(float4*)&OUT[(size_t)row * 512 + n0 + tx * 8 + 4] = make_float4(f4, f5, f6, f7);
    }
}

// ============================================================
// Recurrent kernel: R11 base (best: 1.792ms). ONE change:
// warps 0-3 each wait the s-mbarrier directly, compute softmax
// redundantly in registers, and fuse htilde — removing the warp0
// softmax funnel and one __syncthreads per step.
// ============================================================
__global__ __launch_bounds__(RTHREADS, 1) __cluster_dims__(RANKS, 1, 1)
void recurrent_kernel(const float* __restrict__ Hm,
                      const float* __restrict__ v,
                      const float* __restrict__ W3,
                      float* __restrict__ out)
{
    __shared__ float4   hts4[COLS];                  // (h0,h0,h1,h1) per own col
    __shared__ float    thist[NS][BPC][COLS];        // htilde history
    __shared__ float    ghist[NS][BPC][COLS];        // summed g history
    __shared__ uint64_t gpartB[RANKS][2][BPC][32];   // [src][khalf][bl][pair]
    __shared__ float    spart[2][BPC][NS][RANKS];    // logit partials, parity
    __shared__ float    pbufA[2][BPC * NS][COLS];    // prefetched g_A rows
    __shared__ float    pbufC[2][BPC][COLS];         // prefetched g_C rows
    __shared__ float    hbuf[2][BPC][COLS];          // prefetched H rows
    __shared__ float    vsm[COLS];
    __shared__ uint64_t mbars[6];                    // [0..1]=g ring, [2..5]=s ring

    const int tid  = threadIdx.x;
    const int warp = tid >> 5, lane = tid & 31;
    const int rank = blockIdx.x & (RANKS - 1);
    const int cl   = blockIdx.x >> 3;
    const int col0 = rank * COLS;
    const int b0   = cl * BPC;

    const uint32_t mg_base = su32(&mbars[0]);        // + 8*b  (b = 0,1)
    const uint32_t ms_base = su32(&mbars[2]);        // + 8*k  (k = 0..3)

    // ---- init mbarriers, then cluster-wide visibility ----
    if (tid == 0) {
        #pragma unroll
        for (int i = 0; i < 6; i++) mbar_init(su32(&mbars[i]), 1);
        mbar_arrive_expect(mg_base + 0, TX_G);       // g data t=0
        mbar_arrive_expect(mg_base + 8, TX_G);       // g data t=1
        #pragma unroll
        for (int k = 0; k < 4; k++) mbar_arrive_expect(ms_base + 8 * k, TX_S);
    }
    if (tid < COLS) vsm[tid] = v[col0 + tid];
    for (int i = tid; i < NS * BPC * COLS; i += RTHREADS) {
        ((float*)ghist)[i] = 0.f;
        ((float*)thist)[i] = 0.f;
    }
    __syncthreads();
    cluster_sync();   // all mbarriers initialized before any remote st.async

    // ---- P3 identities: thread owns col pair (2p, 2p+1), k-half ----
    const int pairIdx = tid & 255;
    const int khalf   = tid >> 8;
    const int gcol    = pairIdx * 2;
    const int gdst    = pairIdx >> 5;                // destination rank
    const uint32_t grd0 = mapa_u32(su32(&gpartB[rank][khalf][0][pairIdx & 31]), gdst);
    const uint32_t grd1 = mapa_u32(su32(&gpartB[rank][khalf][1][pairIdx & 31]), gdst);
    uint32_t grm[2];
    grm[0] = mapa_u32(mg_base + 0, gdst);
    grm[1] = mapa_u32(mg_base + 8, gdst);

    // W3 slice: 32 k-rows x 2 adjacent cols, pair-packed
    uint64_t w3p[32];
    #pragma unroll
    for (int kk = 0; kk < 32; kk++)
        w3p[kk] = *(const uint64_t*)&W3[(size_t)(col0 + khalf * 32 + kk) * D + gcol];

    // loader ids (warps 10-15)
    const int lidx = tid - 320;
    const int lrow = lidx >> 4;            // 0..11
    const int lq   = (lidx & 15) * 4;
    const int lbl  = (lidx >> 4) & 1;

    // P1 ids
    const int p1bl = (warp < 10) ? warp / NS : 0;
    const int p1i  = (warp < 10) ? warp % NS : 0;
    const int d0   = lane * 2;
    uint32_t spush[2];
    spush[0] = su32(&spart[0][p1bl][p1i][rank]);
    spush[1] = su32(&spart[1][p1bl][p1i][rank]);

    // htilde/softmax ids (warps 0-3)
    const int hbl = warp >> 1;
    const int hdd = ((warp & 1) << 5) + lane;

    // ---- prologue: load t=0 C/H rows ----
    if (warp >= 10) {
        if (lrow >= 10)
            *(float4*)&pbufC[0][lrow - 10][lq] =
                __ldcs((const float4*)&g_C[((size_t)(b0 + lrow - 10) * S + 0) * D + col0 + lq]);
        if (lidx < 32)
            *(float4*)&hbuf[0][lbl][lq] =
                *(const float4*)&Hm[((size_t)(b0 + lbl) * S + 0) * D + col0 + lq];
    }
    __syncthreads();

    // prologue P1-pre for t=0 (i<4 warps; all j<0 -> c-only)
    if (warp < 10 && p1i != NS - 1) {
        float2 c2 = *(float2*)&pbufC[0][p1bl][d0];
        float val = ftanh(c2.x) * vsm[d0] + ftanh(c2.y) * vsm[d0 + 1];
        #pragma unroll
        for (int o = 16; o > 0; o >>= 1)
            val += __shfl_down_sync(0xffffffffu, val, o);
        if (lane == 0) {
            #pragma unroll
            for (int r = 0; r < RANKS; r++)
                stasync_b32(spush[0], ms_base + 0, r, __float_as_uint(val));
        }
    }

    // prologue: issue LDGs for t=1
    float4 pvA = make_float4(0.f, 0.f, 0.f, 0.f);
    float4 pvH = make_float4(0.f, 0.f, 0.f, 0.f);
    int pfrow = -1; bool pfH = false;
    if (warp >= 10) {
        if (lrow < 10) {
            int jbl = lrow / NS, ji = lrow % NS, j = 1 - NS + ji;
            if (j >= 0) {
                pvA = __ldcs((const float4*)&g_A[((size_t)(b0 + jbl) * S + j) * D + col0 + lq]);
                pfrow = lrow;
            }
        } else {
            pvA = __ldcs((const float4*)&g_C[((size_t)(b0 + lrow - 10) * S + 1) * D + col0 + lq]);
            pfrow = lrow;
        }
        if (lidx < 32) {
            pvH = *(const float4*)&Hm[((size_t)(b0 + lbl) * S + 1) * D + col0 + lq];
            pfH = true;
        }
    }

    for (int t = 0; t < S; t++) {
        const int par = t & 1;
        const int sk  = t & 3;

        // ---- critical warps (4, 9): wait g(t-1), sum, logit, push s ----
        if (warp < 10 && p1i == NS - 1) {
            const int j = t - 1;
            if (j >= 0) {
                const int gb = j & 1;
                mbar_wait(mg_base + 8 * gb, (j >> 1) & 1);
                if (warp == 4 && lane == 0)   // re-arm for data t+1
                    mbar_arrive_expect(mg_base + 8 * gb, TX_G);
            }
            float2 c2 = *(float2*)&pbufC[par][p1bl][d0];
            float x0 = c2.x, x1 = c2.y;
            if (j >= 0) {
                float2 a2 = *(float2*)&pbufA[par][warp][d0];
                uint64_t s = 0ull;
                #pragma unroll
                for (int r = 0; r < RANKS; r++) {
                    s = add2(s, gpartB[r][0][p1bl][lane]);
                    s = add2(s, gpartB[r][1][p1bl][lane]);
                }
                float g0, g1;
                unpack2(s, g0, g1);
                *(float2*)&ghist[j % NS][p1bl][d0] = make_float2(g0, g1);
                x0 += a2.x + g0;
                x1 += a2.y + g1;
            }
            float val = ftanh(x0) * vsm[d0] + ftanh(x1) * vsm[d0 + 1];
            #pragma unroll
            for (int o = 16; o > 0; o >>= 1)
                val += __shfl_down_sync(0xffffffffu, val, o);
            if (lane == 0) {
                #pragma unroll
                for (int r = 0; r < RANKS; r++)
                    stasync_b32(spush[par], ms_base + 8 * sk, r, __float_as_uint(val));
            }
        }

        // ---- warps 0-3: wait s, redundant register softmax, htilde ----
        if (warp < 4) {
            mbar_wait(ms_base + 8 * sk, (t >> 2) & 1);
            if (warp == 0 && lane == 0)
                mbar_arrive_expect(ms_base + 8 * sk, TX_S);   // re-arm for t+4

            float sv[NS];
            #pragma unroll
            for (int i = 0; i < NS; i++) {
                float4 u0 = *(float4*)&spart[par][hbl][i][0];
                float4 u1 = *(float4*)&spart[par][hbl][i][4];
                sv[i] = (u0.x + u0.y + u0.z + u0.w) + (u1.x + u1.y + u1.z + u1.w);
            }
            float m = sv[0];
            #pragma unroll
            for (int i = 1; i < NS; i++) m = fmaxf(m, sv[i]);
            float e[NS], sum = 0.f;
            #pragma unroll
            for (int i = 0; i < NS; i++) { e[i] = __expf(sv[i] - m); sum += e[i]; }
            float inv = __fdividef(1.f, sum);

            float hh = 0.f;
            #pragma unroll
            for (int i = 0; i < NS; i++) {
                int j = t - NS + i;
                if (j >= 0) hh += (e[i] * inv) * thist[j % NS][hbl][hdd];
            }
            float hv = hbuf[par][hbl][hdd] + fmaxf(hh, 0.f);
            thist[t % NS][hbl][hdd] = hv;
            *(float2*)((float*)&hts4[hdd] + 2 * hbl) = make_float2(hv, hv);
            __stcs(&out[((size_t)(b0 + hbl) * S + t) * D + col0 + hdd], hv);
        }

        // ---- loader warps: deposit t+1, issue LDG t+2 ----
        if (warp >= 10) {
            if (pfrow >= 0) {
                if (pfrow < 10) *(float4*)&pbufA[par ^ 1][pfrow][lq]      = pvA;
                else            *(float4*)&pbufC[par ^ 1][pfrow - 10][lq] = pvA;
            }
            if (pfH) *(float4*)&hbuf[par ^ 1][lbl][lq] = pvH;
            pfrow = -1; pfH = false;
            const int tload = t + 2;
            if (tload < S) {
                if (lrow < 10) {
                    int jbl = lrow / NS, ji = lrow % NS, j = tload - NS + ji;
                    if (j >= 0) {
                        pvA = __ldcs((const float4*)&g_A[((size_t)(b0 + jbl) * S + j) * D + col0 + lq]);
                        pfrow = lrow;
                    }
                } else {
                    pvA = __ldcs((const float4*)&g_C[((size_t)(b0 + lrow - 10) * S + tload) * D + col0 + lq]);
                    pfrow = lrow;
                }
                if (lidx < 32) {
                    pvH = *(const float4*)&Hm[((size_t)(b0 + lbl) * S + tload) * D + col0 + lq];
                    pfH = true;
                }
            }
        }
        __syncthreads();   // single block barrier per step: hts4 ready

        if (t < S - 1) {
            // ---- P3: partial g over k-half, 2 cols x 2 batches ----
            // one LDS.128 broadcast per k: (h0,h0,h1,h1)
            uint64_t acc0 = 0ull, acc1 = 0ull;
            #pragma unroll
            for (int kk = 0; kk < 32; kk++) {
                float4 h = hts4[khalf * 32 + kk];
                acc0 = fma2(pack2(h.x, h.y), w3p[kk], acc0);
                acc1 = fma2(pack2(h.z, h.w), w3p[kk], acc1);
            }
            stasync_b64_pre(grd0, grm[par], acc0);
            stasync_b64_pre(grd1, grm[par], acc1);

            // ---- P1-pre for t+1 (i<4 warps) ----
            if (warp < 10 && p1i != NS - 1) {
                float2 c2 = *(float2*)&pbufC[par ^ 1][p1bl][d0];
                float x0 = c2.x, x1 = c2.y;
                const int j = (t + 1) - NS + p1i;
                if (j >= 0) {
                    float2 a2 = *(float2*)&pbufA[par ^ 1][warp][d0];
                    float2 g2 = *(float2*)&ghist[j % NS][p1bl][d0];
                    x0 += a2.x + g2.x;
                    x1 += a2.y + g2.y;
                }
                float val = ftanh(x0) * vsm[d0] + ftanh(x1) * vsm[d0 + 1];
                #pragma unroll
                for (int o = 16; o > 0; o >>= 1)
                    val += __shfl_down_sync(0xffffffffu, val, o);
                if (lane == 0) {
                    #pragma unroll
                    for (int r = 0; r < RANKS; r++)
                        stasync_b32(spush[par ^ 1], ms_base + 8 * ((t + 1) & 3), r,
                                    __float_as_uint(val));
                }
            }
        }
    }

    // Terminal cluster sync: no CTA exits while peers' remote stores could
    // still target its SMEM / mbarriers.
    cluster_sync();
}

// ============================================================
// Launch
// ============================================================
extern "C" void kernel_launch(void* const* d_in, const int* in_sizes, int n_in,
                              void* d_out, int out_size)
{
    (void)in_sizes; (void)n_in; (void)out_size;
    const float* H  = (const float*)d_in[0];
    const float* v  = (const float*)d_in[1];
    const float* W1 = (const float*)d_in[2];
    const float* W2 = (const float*)d_in[3];
    const float* W3 = (const float*)d_in[4];
    float* out = (float*)d_out;

    precompute_kernel<<<dim3((B * S) / PM, 8), 256>>>(H, W1, W2);
    recurrent_kernel<<<NCLUSTERS * RANKS, RTHREADS>>>(H, v, W3, out);
}

// round 13
// speedup vs baseline: 1.4295x; 1.0364x over previous
#include <cuda_runtime.h>
#include <cstdint>

#define DEV_INLINE __device__ __forceinline__

// Problem constants
constexpr int B  = 32;
constexpr int S  = 512;
constexpr int D  = 512;
constexpr int NS = 5;

// Recurrent kernel tiling
constexpr int RANKS     = 8;            // CTAs per cluster
constexpr int BPC       = 2;            // batches per cluster
constexpr int NCLUSTERS = B / BPC;      // 16
constexpr int COLS      = D / RANKS;    // 64 columns per CTA
constexpr int RTHREADS  = 512;

// mbarrier tx budgets (bytes)
constexpr uint32_t TX_G    = 8192;  // 512 thr * 2 * 8B from 8 src ranks total
constexpr uint32_t TX_PRE  = 256;   // 8 pre warps * 8 src CTAs * 4B
constexpr uint32_t TX_CRIT = 64;    // 2 crit warps * 8 src CTAs * 4B

// Scratch (static device arrays; no allocations allowed)
__device__ float g_A[(size_t)B * S * D];       // H @ W1
__device__ float g_C[(size_t)B * S * D];       // H @ W2

// ---------- helpers ----------
DEV_INLINE uint64_t pack2(float lo, float hi) {
    uint64_t r; asm("mov.b64 %0, {%1, %2};" : "=l"(r) : "f"(lo), "f"(hi)); return r;
}
DEV_INLINE void unpack2(uint64_t v, float& lo, float& hi) {
    asm("mov.b64 {%0, %1}, %2;" : "=f"(lo), "=f"(hi) : "l"(v));
}
DEV_INLINE uint64_t fma2(uint64_t a, uint64_t b, uint64_t c) {
    uint64_t d; asm("fma.rn.f32x2 %0, %1, %2, %3;" : "=l"(d) : "l"(a), "l"(b), "l"(c));
    return d;
}
DEV_INLINE uint64_t add2(uint64_t a, uint64_t b) {
    uint64_t d; asm("add.rn.f32x2 %0, %1, %2;" : "=l"(d) : "l"(a), "l"(b));
    return d;
}
DEV_INLINE uint32_t su32(const void* p) {
    uint32_t a;
    asm("{ .reg .u64 t; cvta.to.shared.u64 t, %1; cvt.u32.u64 %0, t; }" : "=r"(a) : "l"(p));
    return a;
}
DEV_INLINE uint32_t mapa_u32(uint32_t a, int rank) {
    uint32_t r; asm("mapa.shared::cluster.u32 %0, %1, %2;" : "=r"(r) : "r"(a), "r"(rank));
    return r;
}
// Remote store with mbarrier tx-completion (data+mbar in SAME target CTA)
DEV_INLINE void stasync_b32(uint32_t daddr, uint32_t mbar, int rank, uint32_t v) {
    asm volatile(
        "{ .reg .b32 rd, rm;\n\t"
        "mapa.shared::cluster.u32 rd, %0, %2;\n\t"
        "mapa.shared::cluster.u32 rm, %1, %2;\n\t"
        "st.async.shared::cluster.mbarrier::complete_tx::bytes.b32 [rd], %3, [rm]; }"
        :: "r"(daddr), "r"(mbar), "r"(rank), "r"(v) : "memory");
}
DEV_INLINE void stasync_b64_pre(uint32_t rdaddr, uint32_t rmbar, uint64_t v) {
    asm volatile(
        "st.async.shared::cluster.mbarrier::complete_tx::bytes.b64 [%0], %1, [%2];"
        :: "r"(rdaddr), "l"(v), "r"(rmbar) : "memory");
}
DEV_INLINE void mbar_init(uint32_t a, uint32_t cnt) {
    asm volatile("mbarrier.init.shared.b64 [%0], %1;" :: "r"(a), "r"(cnt) : "memory");
}
DEV_INLINE void mbar_arrive_expect(uint32_t a, uint32_t tx) {
    asm volatile("mbarrier.arrive.expect_tx.shared.b64 _, [%0], %1;"
                 :: "r"(a), "r"(tx) : "memory");
}
// CTA-scope acquire: st.async complete_tx fires after data is visible in
// OUR local smem (same contract as TMA complete_tx consumers). R8-proven.
DEV_INLINE void mbar_wait(uint32_t mbar, uint32_t parity) {
    asm volatile(
        "{\n\t"
        ".reg .pred P;\n\t"
        "WAIT_%=:\n\t"
        "mbarrier.try_wait.parity.acquire.cta.shared::cta.b64 P, [%0], %1, 0x989680;\n\t"
        "@P bra.uni DONE_%=;\n\t"
        "bra.uni WAIT_%=;\n\t"
        "DONE_%=:\n\t"
        "}"
        :: "r"(mbar), "r"(parity) : "memory");
}
DEV_INLINE void cluster_sync() {
    asm volatile("barrier.cluster.arrive.aligned;" ::: "memory");
    asm volatile("barrier.cluster.wait.aligned;"   ::: "memory");
}
// fast tanh via __expf, clamped so exp never overflows
DEV_INLINE float ftanh(float x) {
    x = fminf(15.f, fmaxf(-15.f, x));
    float e = __expf(x + x);
    return __fdividef(e - 1.f, e + 1.f);
}

// ============================================================
// Precompute: A = H @ W1, C = H @ W2   (fp32, f32x2 FMAs)
// ============================================================
constexpr int PM = 128, PN = 128, PK = 16;

__global__ __launch_bounds__(256) void precompute_kernel(
    const float* __restrict__ Hm,
    const float* __restrict__ W1,
    const float* __restrict__ W2)
{
    __shared__ float As[PK][PM];
    __shared__ float Bs[PK][PN];

    const int tid   = threadIdx.x;
    const int which = blockIdx.y >> 2;
    const int n0    = (blockIdx.y & 3) * PN;
    const int m0    = blockIdx.x * PM;
    const float* W  = which ? W2 : W1;
    float* OUT      = which ? g_C : g_A;

    const int tx = tid & 15;
    const int ty = tid >> 4;

    uint64_t acc[8][4];
    #pragma unroll
    for (int i = 0; i < 8; i++)
        #pragma unroll
        for (int j = 0; j < 4; j++) acc[i][j] = 0ull;

    for (int kt = 0; kt < 512; kt += PK) {
        #pragma unroll
        for (int i = 0; i < 2; i++) {
            int idx4 = i * 256 + tid;
            int m  = idx4 >> 2;
            int kq = (idx4 & 3) * 4;
            float4 vv = *(const float4*)&Hm[(size_t)(m0 + m) * 512 + kt + kq];
            As[kq + 0][m] = vv.x; As[kq + 1][m] = vv.y;
            As[kq + 2][m] = vv.z; As[kq + 3][m] = vv.w;
        }
        #pragma unroll
        for (int i = 0; i < 2; i++) {
            int idx4 = i * 256 + tid;
            int n4 = (idx4 & 31) * 4;
            int k  = idx4 >> 5;
            *(float4*)&Bs[k][n4] = *(const float4*)&W[(size_t)(kt + k) * 512 + n0 + n4];
        }
        __syncthreads();

        #pragma unroll
        for (int k = 0; k < PK; k++) {
            float4 a0 = *(const float4*)&As[k][ty * 8];
            float4 a1 = *(const float4*)&As[k][ty * 8 + 4];
            float4 b0 = *(const float4*)&Bs[k][tx * 8];
            float4 b1 = *(const float4*)&Bs[k][tx * 8 + 4];
            float av[8] = {a0.x, a0.y, a0.z, a0.w, a1.x, a1.y, a1.z, a1.w};
            uint64_t bp[4];
            bp[0] = pack2(b0.x, b0.y); bp[1] = pack2(b0.z, b0.w);
            bp[2] = pack2(b1.x, b1.y); bp[3] = pack2(b1.z, b1.w);
            #pragma unroll
            for (int i = 0; i < 8; i++) {
                uint64_t ad = pack2(av[i], av[i]);
                #pragma unroll
                for (int j = 0; j < 4; j++)
                    acc[i][j] = fma2(ad, bp[j], acc[i][j]);
            }
        }
        __syncthreads();
    }

    #pragma unroll
    for (int i = 0; i < 8; i++) {
        int row = m0 + ty * 8 + i;
        float f0, f1, f2, f3, f4, f5, f6, f7;
        unpack2(acc[i][0], f0, f1); unpack2(acc[i][1], f2, f3);
        unpack2(acc[i][2], f4, f5); unpack2(acc[i][3], f6, f7);
        *(float4*)&OUT[(size_t)row * 512 + n0 + tx * 8]     = make_float4(f0, f1, f2, f3);
        *(float4*)&OUT[(size_t)row * 512 + n0 + tx * 8 + 4] = make_float4(f4, f5, f6, f7);
    }
}

// ============================================================
// Recurrent kernel: R12 base (best: 1.568ms). ONE change:
// s-exchange split into ms_pre (4 early slots) + ms_crit (late slot).
// htilde warps compute the 4-slot partial softmax BEFORE waiting on
// the critical mbarrier, then fold s4 with an online-softmax rescale.
// ============================================================
__global__ __launch_bounds__(RTHREADS, 1) __cluster_dims__(RANKS, 1, 1)
void recurrent_kernel(const float* __restrict__ Hm,
                      const float* __restrict__ v,
                      const float* __restrict__ W3,
                      float* __restrict__ out)
{
    __shared__ float4   hts4[COLS];                  // (h0,h0,h1,h1) per own col
    __shared__ float    thist[NS][BPC][COLS];        // htilde history
    __shared__ float    ghist[NS][BPC][COLS];        // summed g history
    __shared__ uint64_t gpartB[RANKS][2][BPC][32];   // [src][khalf][bl][pair]
    __shared__ float    spart[2][BPC][NS][RANKS];    // logit partials, parity
    __shared__ float    pbufA[2][BPC * NS][COLS];    // prefetched g_A rows
    __shared__ float    pbufC[2][BPC][COLS];         // prefetched g_C rows
    __shared__ float    hbuf[2][BPC][COLS];          // prefetched H rows
    __shared__ float    vsm[COLS];
    __shared__ uint64_t mbars[10];   // [0..1]=g, [2..5]=s_pre, [6..9]=s_crit

    const int tid  = threadIdx.x;
    const int warp = tid >> 5, lane = tid & 31;
    const int rank = blockIdx.x & (RANKS - 1);
    const int cl   = blockIdx.x >> 3;
    const int col0 = rank * COLS;
    const int b0   = cl * BPC;

    const uint32_t mg_base  = su32(&mbars[0]);       // + 8*b  (b = 0,1)
    const uint32_t msp_base = su32(&mbars[2]);       // + 8*k  (k = 0..3) pre
    const uint32_t msc_base = su32(&mbars[6]);       // + 8*k  (k = 0..3) crit

    // ---- init mbarriers, then cluster-wide visibility ----
    if (tid == 0) {
        #pragma unroll
        for (int i = 0; i < 10; i++) mbar_init(su32(&mbars[i]), 1);
        mbar_arrive_expect(mg_base + 0, TX_G);       // g data t=0
        mbar_arrive_expect(mg_base + 8, TX_G);       // g data t=1
        #pragma unroll
        for (int k = 0; k < 4; k++) {
            mbar_arrive_expect(msp_base + 8 * k, TX_PRE);
            mbar_arrive_expect(msc_base + 8 * k, TX_CRIT);
        }
    }
    if (tid < COLS) vsm[tid] = v[col0 + tid];
    for (int i = tid; i < NS * BPC * COLS; i += RTHREADS) {
        ((float*)ghist)[i] = 0.f;
        ((float*)thist)[i] = 0.f;
    }
    __syncthreads();
    cluster_sync();   // all mbarriers initialized before any remote st.async

    // ---- P3 identities: thread owns col pair (2p, 2p+1), k-half ----
    const int pairIdx = tid & 255;
    const int khalf   = tid >> 8;
    const int gcol    = pairIdx * 2;
    const int gdst    = pairIdx >> 5;                // destination rank
    const uint32_t grd0 = mapa_u32(su32(&gpartB[rank][khalf][0][pairIdx & 31]), gdst);
    const uint32_t grd1 = mapa_u32(su32(&gpartB[rank][khalf][1][pairIdx & 31]), gdst);
    uint32_t grm[2];
    grm[0] = mapa_u32(mg_base + 0, gdst);
    grm[1] = mapa_u32(mg_base + 8, gdst);

    // W3 slice: 32 k-rows x 2 adjacent cols, pair-packed
    uint64_t w3p[32];
    #pragma unroll
    for (int kk = 0; kk < 32; kk++)
        w3p[kk] = *(const uint64_t*)&W3[(size_t)(col0 + khalf * 32 + kk) * D + gcol];

    // loader ids (warps 10-15)
    const int lidx = tid - 320;
    const int lrow = lidx >> 4;            // 0..11
    const int lq   = (lidx & 15) * 4;
    const int lbl  = (lidx >> 4) & 1;

    // P1 ids
    const int p1bl = (warp < 10) ? warp / NS : 0;
    const int p1i  = (warp < 10) ? warp % NS : 0;
    const int d0   = lane * 2;
    uint32_t spush[2];
    spush[0] = su32(&spart[0][p1bl][p1i][rank]);
    spush[1] = su32(&spart[1][p1bl][p1i][rank]);

    // htilde/softmax ids (warps 0-3)
    const int hbl = warp >> 1;
    const int hdd = ((warp & 1) << 5) + lane;

    // ---- prologue: load t=0 C/H rows ----
    if (warp >= 10) {
        if (lrow >= 10)
            *(float4*)&pbufC[0][lrow - 10][lq] =
                __ldcs((const float4*)&g_C[((size_t)(b0 + lrow - 10) * S + 0) * D + col0 + lq]);
        if (lidx < 32)
            *(float4*)&hbuf[0][lbl][lq] =
                *(const float4*)&Hm[((size_t)(b0 + lbl) * S + 0) * D + col0 + lq];
    }
    __syncthreads();

    // prologue P1-pre for t=0 (i<4 warps; all j<0 -> c-only)
    if (warp < 10 && p1i != NS - 1) {
        float2 c2 = *(float2*)&pbufC[0][p1bl][d0];
        float val = ftanh(c2.x) * vsm[d0] + ftanh(c2.y) * vsm[d0 + 1];
        #pragma unroll
        for (int o = 16; o > 0; o >>= 1)
            val += __shfl_down_sync(0xffffffffu, val, o);
        if (lane == 0) {
            #pragma unroll
            for (int r = 0; r < RANKS; r++)
                stasync_b32(spush[0], msp_base + 0, r, __float_as_uint(val));
        }
    }

    // prologue: issue LDGs for t=1
    float4 pvA = make_float4(0.f, 0.f, 0.f, 0.f);
    float4 pvH = make_float4(0.f, 0.f, 0.f, 0.f);
    int pfrow = -1; bool pfH = false;
    if (warp >= 10) {
        if (lrow < 10) {
            int jbl = lrow / NS, ji = lrow % NS, j = 1 - NS + ji;
            if (j >= 0) {
                pvA = __ldcs((const float4*)&g_A[((size_t)(b0 + jbl) * S + j) * D + col0 + lq]);
                pfrow = lrow;
            }
        } else {
            pvA = __ldcs((const float4*)&g_C[((size_t)(b0 + lrow - 10) * S + 1) * D + col0 + lq]);
            pfrow = lrow;
        }
        if (lidx < 32) {
            pvH = *(const float4*)&Hm[((size_t)(b0 + lbl) * S + 1) * D + col0 + lq];
            pfH = true;
        }
    }

    for (int t = 0; t < S; t++) {
        const int par = t & 1;
        const int sk  = t & 3;

        // ---- critical warps (4, 9): wait g(t-1), sum, logit, push s_crit ----
        if (warp < 10 && p1i == NS - 1) {
            const int j = t - 1;
            if (j >= 0) {
                const int gb = j & 1;
                mbar_wait(mg_base + 8 * gb, (j >> 1) & 1);
                if (warp == 4 && lane == 0)   // re-arm for data t+1
                    mbar_arrive_expect(mg_base + 8 * gb, TX_G);
            }
            float2 c2 = *(float2*)&pbufC[par][p1bl][d0];
            float x0 = c2.x, x1 = c2.y;
            if (j >= 0) {
                float2 a2 = *(float2*)&pbufA[par][warp][d0];
                uint64_t s = 0ull;
                #pragma unroll
                for (int r = 0; r < RANKS; r++) {
                    s = add2(s, gpartB[r][0][p1bl][lane]);
                    s = add2(s, gpartB[r][1][p1bl][lane]);
                }
                float g0, g1;
                unpack2(s, g0, g1);
                *(float2*)&ghist[j % NS][p1bl][d0] = make_float2(g0, g1);
                x0 += a2.x + g0;
                x1 += a2.y + g1;
            }
            float val = ftanh(x0) * vsm[d0] + ftanh(x1) * vsm[d0 + 1];
            #pragma unroll
            for (int o = 16; o > 0; o >>= 1)
                val += __shfl_down_sync(0xffffffffu, val, o);
            if (lane == 0) {
                #pragma unroll
                for (int r = 0; r < RANKS; r++)
                    stasync_b32(spush[par], msc_base + 8 * sk, r, __float_as_uint(val));
            }
        }

        // ---- warps 0-3: pre-wait + partial softmax, crit-wait + fold, htilde ----
        if (warp < 4) {
            // early slots (pushed end of step t-1): likely fast-path wait
            mbar_wait(msp_base + 8 * sk, (t >> 2) & 1);
            if (warp == 0 && lane == 0)
                mbar_arrive_expect(msp_base + 8 * sk, TX_PRE);   // re-arm t+4

            float sv[NS - 1];
            #pragma unroll
            for (int i = 0; i < NS - 1; i++) {
                float4 u0 = *(float4*)&spart[par][hbl][i][0];
                float4 u1 = *(float4*)&spart[par][hbl][i][4];
                sv[i] = (u0.x + u0.y + u0.z + u0.w) + (u1.x + u1.y + u1.z + u1.w);
            }
            float m4 = sv[0];
            #pragma unroll
            for (int i = 1; i < NS - 1; i++) m4 = fmaxf(m4, sv[i]);
            float e[NS - 1], sum4 = 0.f;
            #pragma unroll
            for (int i = 0; i < NS - 1; i++) { e[i] = __expf(sv[i] - m4); sum4 += e[i]; }

            // late critical slot
            mbar_wait(msc_base + 8 * sk, (t >> 2) & 1);
            if (warp == 0 && lane == 0)
                mbar_arrive_expect(msc_base + 8 * sk, TX_CRIT);  // re-arm t+4
            float4 u0 = *(float4*)&spart[par][hbl][NS - 1][0];
            float4 u1 = *(float4*)&spart[par][hbl][NS - 1][4];
            float s4 = (u0.x + u0.y + u0.z + u0.w) + (u1.x + u1.y + u1.z + u1.w);

            float m   = fmaxf(m4, s4);
            float sc  = __expf(m4 - m);           // rescale for early slots
            float e4  = __expf(s4 - m);
            float inv = __fdividef(1.f, sum4 * sc + e4);
            float wsc = sc * inv;

            float hh = 0.f;
            #pragma unroll
            for (int i = 0; i < NS - 1; i++) {
                int j = t - NS + i;
                if (j >= 0) hh += (e[i] * wsc) * thist[j % NS][hbl][hdd];
            }
            {
                int j4 = t - 1;
                if (j4 >= 0) hh += (e4 * inv) * thist[j4 % NS][hbl][hdd];
            }
            float hv = hbuf[par][hbl][hdd] + fmaxf(hh, 0.f);
            thist[t % NS][hbl][hdd] = hv;
            *(float2*)((float*)&hts4[hdd] + 2 * hbl) = make_float2(hv, hv);
            __stcs(&out[((size_t)(b0 + hbl) * S + t) * D + col0 + hdd], hv);
        }

        // ---- loader warps: deposit t+1, issue LDG t+2 ----
        if (warp >= 10) {
            if (pfrow >= 0) {
                if (pfrow < 10) *(float4*)&pbufA[par ^ 1][pfrow][lq]      = pvA;
                else            *(float4*)&pbufC[par ^ 1][pfrow - 10][lq] = pvA;
            }
            if (pfH) *(float4*)&hbuf[par ^ 1][lbl][lq] = pvH;
            pfrow = -1; pfH = false;
            const int tload = t + 2;
            if (tload < S) {
                if (lrow < 10) {
                    int jbl = lrow / NS, ji = lrow % NS, j = tload - NS + ji;
                    if (j >= 0) {
                        pvA = __ldcs((const float4*)&g_A[((size_t)(b0 + jbl) * S + j) * D + col0 + lq]);
                        pfrow = lrow;
                    }
                } else {
                    pvA = __ldcs((const float4*)&g_C[((size_t)(b0 + lrow - 10) * S + tload) * D + col0 + lq]);
                    pfrow = lrow;
                }
                if (lidx < 32) {
                    pvH = *(const float4*)&Hm[((size_t)(b0 + lbl) * S + tload) * D + col0 + lq];
                    pfH = true;
                }
            }
        }
        __syncthreads();   // single block barrier per step: hts4 ready

        if (t < S - 1) {
            // ---- P3: partial g over k-half, 2 cols x 2 batches ----
            uint64_t acc0 = 0ull, acc1 = 0ull;
            #pragma unroll
            for (int kk = 0; kk < 32; kk++) {
                float4 h = hts4[khalf * 32 + kk];
                acc0 = fma2(pack2(h.x, h.y), w3p[kk], acc0);
                acc1 = fma2(pack2(h.z, h.w), w3p[kk], acc1);
            }
            stasync_b64_pre(grd0, grm[par], acc0);
            stasync_b64_pre(grd1, grm[par], acc1);

            // ---- P1-pre for t+1 (i<4 warps) ----
            if (warp < 10 && p1i != NS - 1) {
                float2 c2 = *(float2*)&pbufC[par ^ 1][p1bl][d0];
                float x0 = c2.x, x1 = c2.y;
                const int j = (t + 1) - NS + p1i;
                if (j >= 0) {
                    float2 a2 = *(float2*)&pbufA[par ^ 1][warp][d0];
                    float2 g2 = *(float2*)&ghist[j % NS][p1bl][d0];
                    x0 += a2.x + g2.x;
                    x1 += a2.y + g2.y;
                }
                float val = ftanh(x0) * vsm[d0] + ftanh(x1) * vsm[d0 + 1];
                #pragma unroll
                for (int o = 16; o > 0; o >>= 1)
                    val += __shfl_down_sync(0xffffffffu, val, o);
                if (lane == 0) {
                    #pragma unroll
                    for (int r = 0; r < RANKS; r++)
                        stasync_b32(spush[par ^ 1], msp_base + 8 * ((t + 1) & 3), r,
                                    __float_as_uint(val));
                }
            }
        }
    }

    // Terminal cluster sync: no CTA exits while peers' remote stores could
    // still target its SMEM / mbarriers.
    cluster_sync();
}

// ============================================================
// Launch
// ============================================================
extern "C" void kernel_launch(void* const* d_in, const int* in_sizes, int n_in,
                              void* d_out, int out_size)
{
    (void)in_sizes; (void)n_in; (void)out_size;
    const float* H  = (const float*)d_in[0];
    const float* v  = (const float*)d_in[1];
    const float* W1 = (const float*)d_in[2];
    const float* W2 = (const float*)d_in[3];
    const float* W3 = (const float*)d_in[4];
    float* out = (float*)d_out;

    precompute_kernel<<<dim3((B * S) / PM, 8), 256>>>(H, W1, W2);
    recurrent_kernel<<<NCLUSTERS * RANKS, RTHREADS>>>(H, v, W3, out);
}

// round 15
// speedup vs baseline: 1.4392x; 1.0068x over previous
#include <cuda_runtime.h>
#include <cstdint>

#define DEV_INLINE __device__ __forceinline__

// Problem constants
constexpr int B  = 32;
constexpr int S  = 512;
constexpr int D  = 512;
constexpr int NS = 5;

// Recurrent kernel tiling
constexpr int RANKS     = 8;            // CTAs per cluster
constexpr int BPC       = 2;            // batches per cluster
constexpr int NCLUSTERS = B / BPC;      // 16
constexpr int COLS      = D / RANKS;    // 64 columns per CTA
constexpr int RTHREADS  = 512;

// mbarrier tx budgets (bytes)
constexpr uint32_t TX_G    = 8192;  // 512 thr * 2 * 8B from 8 src ranks total
constexpr uint32_t TX_PRE  = 256;   // 8 pre warps * 8 src CTAs * 4B
constexpr uint32_t TX_CRIT = 64;    // 2 crit warps * 8 src CTAs * 4B

// Scratch (static device arrays; no allocations allowed)
__device__ float g_A[(size_t)B * S * D];       // H @ W1
__device__ float g_C[(size_t)B * S * D];       // H @ W2

// ---------- helpers ----------
DEV_INLINE uint64_t pack2(float lo, float hi) {
    uint64_t r; asm("mov.b64 %0, {%1, %2};" : "=l"(r) : "f"(lo), "f"(hi)); return r;
}
DEV_INLINE void unpack2(uint64_t v, float& lo, float& hi) {
    asm("mov.b64 {%0, %1}, %2;" : "=f"(lo), "=f"(hi) : "l"(v));
}
DEV_INLINE uint64_t fma2(uint64_t a, uint64_t b, uint64_t c) {
    uint64_t d; asm("fma.rn.f32x2 %0, %1, %2, %3;" : "=l"(d) : "l"(a), "l"(b), "l"(c));
    return d;
}
DEV_INLINE uint64_t add2(uint64_t a, uint64_t b) {
    uint64_t d; asm("add.rn.f32x2 %0, %1, %2;" : "=l"(d) : "l"(a), "l"(b));
    return d;
}
// butterfly warp sum: result in ALL lanes (sm_103-legal)
DEV_INLINE float warp_sum_all(float x) {
    #pragma unroll
    for (int o = 16; o > 0; o >>= 1)
        x += __shfl_xor_sync(0xffffffffu, x, o);
    return x;
}
DEV_INLINE uint32_t su32(const void* p) {
    uint32_t a;
    asm("{ .reg .u64 t; cvta.to.shared.u64 t, %1; cvt.u32.u64 %0, t; }" : "=r"(a) : "l"(p));
    return a;
}
DEV_INLINE uint32_t mapa_u32(uint32_t a, int rank) {
    uint32_t r; asm("mapa.shared::cluster.u32 %0, %1, %2;" : "=r"(r) : "r"(a), "r"(rank));
    return r;
}
// Remote store with mbarrier tx-completion (data+mbar in SAME target CTA)
DEV_INLINE void stasync_b32(uint32_t daddr, uint32_t mbar, int rank, uint32_t v) {
    asm volatile(
        "{ .reg .b32 rd, rm;\n\t"
        "mapa.shared::cluster.u32 rd, %0, %2;\n\t"
        "mapa.shared::cluster.u32 rm, %1, %2;\n\t"
        "st.async.shared::cluster.mbarrier::complete_tx::bytes.b32 [rd], %3, [rm]; }"
        :: "r"(daddr), "r"(mbar), "r"(rank), "r"(v) : "memory");
}
DEV_INLINE void stasync_b64_pre(uint32_t rdaddr, uint32_t rmbar, uint64_t v) {
    asm volatile(
        "st.async.shared::cluster.mbarrier::complete_tx::bytes.b64 [%0], %1, [%2];"
        :: "r"(rdaddr), "l"(v), "r"(rmbar) : "memory");
}
DEV_INLINE void mbar_init(uint32_t a, uint32_t cnt) {
    asm volatile("mbarrier.init.shared.b64 [%0], %1;" :: "r"(a), "r"(cnt) : "memory");
}
DEV_INLINE void mbar_arrive_expect(uint32_t a, uint32_t tx) {
    asm volatile("mbarrier.arrive.expect_tx.shared.b64 _, [%0], %1;"
                 :: "r"(a), "r"(tx) : "memory");
}
// CTA-scope acquire: st.async complete_tx fires after data is visible in
// OUR local smem (same contract as TMA complete_tx consumers). R8-proven.
DEV_INLINE void mbar_wait(uint32_t mbar, uint32_t parity) {
    asm volatile(
        "{\n\t"
        ".reg .pred P;\n\t"
        "WAIT_%=:\n\t"
        "mbarrier.try_wait.parity.acquire.cta.shared::cta.b64 P, [%0], %1, 0x989680;\n\t"
        "@P bra.uni DONE_%=;\n\t"
        "bra.uni WAIT_%=;\n\t"
        "DONE_%=:\n\t"
        "}"
        :: "r"(mbar), "r"(parity) : "memory");
}
DEV_INLINE void cluster_sync() {
    asm volatile("barrier.cluster.arrive.aligned;" ::: "memory");
    asm volatile("barrier.cluster.wait.aligned;"   ::: "memory");
}
// fast tanh via __expf, clamped so exp never overflows
DEV_INLINE float ftanh(float x) {
    x = fminf(15.f, fmaxf(-15.f, x));
    float e = __expf(x + x);
    return __fdividef(e - 1.f, e + 1.f);
}

// ============================================================
// Precompute: A = H @ W1, C = H @ W2   (fp32, f32x2 FMAs)
// ============================================================
constexpr int PM = 128, PN = 128, PK = 16;

__global__ __launch_bounds__(256) void precompute_kernel(
    const float* __restrict__ Hm,
    const float* __restrict__ W1,
    const float* __restrict__ W2)
{
    __shared__ float As[PK][PM];
    __shared__ float Bs[PK][PN];

    const int tid   = threadIdx.x;
    const int which = blockIdx.y >> 2;
    const int n0    = (blockIdx.y & 3) * PN;
    const int m0    = blockIdx.x * PM;
    const float* W  = which ? W2 : W1;
    float* OUT      = which ? g_C : g_A;

    const int tx = tid & 15;
    const int ty = tid >> 4;

    uint64_t acc[8][4];
    #pragma unroll
    for (int i = 0; i < 8; i++)
        #pragma unroll
        for (int j = 0; j < 4; j++) acc[i][j] = 0ull;

    for (int kt = 0; kt < 512; kt += PK) {
        #pragma unroll
        for (int i = 0; i < 2; i++) {
            int idx4 = i * 256 + tid;
            int m  = idx4 >> 2;
            int kq = (idx4 & 3) * 4;
            float4 vv = *(const float4*)&Hm[(size_t)(m0 + m) * 512 + kt + kq];
            As[kq + 0][m] = vv.x; As[kq + 1][m] = vv.y;
            As[kq + 2][m] = vv.z; As[kq + 3][m] = vv.w;
        }
        #pragma unroll
        for (int i = 0; i < 2; i++) {
            int idx4 = i * 256 + tid;
            int n4 = (idx4 & 31) * 4;
            int k  = idx4 >> 5;
            *(float4*)&Bs[k][n4] = *(const float4*)&W[(size_t)(kt + k) * 512 + n0 + n4];
        }
        __syncthreads();

        #pragma unroll
        for (int k = 0; k < PK; k++) {
            float4 a0 = *(const float4*)&As[k][ty * 8];
            float4 a1 = *(const float4*)&As[k][ty * 8 + 4];
            float4 b0 = *(const float4*)&Bs[k][tx * 8];
            float4 b1 = *(const float4*)&Bs[k][tx * 8 + 4];
            float av[8] = {a0.x, a0.y, a0.z, a0.w, a1.x, a1.y, a1.z, a1.w};
            uint64_t bp[4];
            bp[0] = pack2(b0.x, b0.y); bp[1] = pack2(b0.z, b0.w);
            bp[2] = pack2(b1.x, b1.y); bp[3] = pack2(b1.z, b1.w);
            #pragma unroll
            for (int i = 0; i < 8; i++) {
                uint64_t ad = pack2(av[i], av[i]);
                #pragma unroll
                for (int j = 0; j < 4; j++)
                    acc[i][j] = fma2(ad, bp[j], acc[i][j]);
            }
        }
        __syncthreads();
    }

    #pragma unroll
    for (int i = 0; i < 8; i++) {
        int row = m0 + ty * 8 + i;
        float f0, f1, f2, f3, f4, f5, f6, f7;
        unpack2(acc[i][0], f0, f1); unpack2(acc[i][1], f2, f3);
        unpack2(acc[i][2], f4, f5); unpack2(acc[i][3], f6, f7);
        *(float4*)&OUT[(size_t)row * 512 + n0 + tx * 8]     = make_float4(f0, f1, f2, f3);
        *(float4*)&OUT[(size_t)row * 512 + n0 + tx * 8 + 4] = make_float4(f4, f5, f6, f7);
    }
}

// ============================================================
// Recurrent kernel: R13 base (best: 1.494ms). ONE coupled change
// (ISA-legal version of R14): shfl_xor butterfly leaves the warp sum
// in ALL lanes; the 8 remote s-pushes are spread across lanes 0-7
// (lane r -> rank r) instead of 8 serial pushes by lane 0.
// ============================================================
__global__ __launch_bounds__(RTHREADS, 1) __cluster_dims__(RANKS, 1, 1)
void recurrent_kernel(const float* __restrict__ Hm,
                      const float* __restrict__ v,
                      const float* __restrict__ W3,
                      float* __restrict__ out)
{
    __shared__ float4   hts4[COLS];                  // (h0,h0,h1,h1) per own col
    __shared__ float    thist[NS][BPC][COLS];        // htilde history
    __shared__ float    ghist[NS][BPC][COLS];        // summed g history
    __shared__ uint64_t gpartB[RANKS][2][BPC][32];   // [src][khalf][bl][pair]
    __shared__ float    spart[2][BPC][NS][RANKS];    // logit partials, parity
    __shared__ float    pbufA[2][BPC * NS][COLS];    // prefetched g_A rows
    __shared__ float    pbufC[2][BPC][COLS];         // prefetched g_C rows
    __shared__ float    hbuf[2][BPC][COLS];          // prefetched H rows
    __shared__ float    vsm[COLS];
    __shared__ uint64_t mbars[10];   // [0..1]=g, [2..5]=s_pre, [6..9]=s_crit

    const int tid  = threadIdx.x;
    const int warp = tid >> 5, lane = tid & 31;
    const int rank = blockIdx.x & (RANKS - 1);
    const int cl   = blockIdx.x >> 3;
    const int col0 = rank * COLS;
    const int b0   = cl * BPC;

    const uint32_t mg_base  = su32(&mbars[0]);       // + 8*b  (b = 0,1)
    const uint32_t msp_base = su32(&mbars[2]);       // + 8*k  (k = 0..3) pre
    const uint32_t msc_base = su32(&mbars[6]);       // + 8*k  (k = 0..3) crit

    // ---- init mbarriers, then cluster-wide visibility ----
    if (tid == 0) {
        #pragma unroll
        for (int i = 0; i < 10; i++) mbar_init(su32(&mbars[i]), 1);
        mbar_arrive_expect(mg_base + 0, TX_G);       // g data t=0
        mbar_arrive_expect(mg_base + 8, TX_G);       // g data t=1
        #pragma unroll
        for (int k = 0; k < 4; k++) {
            mbar_arrive_expect(msp_base + 8 * k, TX_PRE);
            mbar_arrive_expect(msc_base + 8 * k, TX_CRIT);
        }
    }
    if (tid < COLS) vsm[tid] = v[col0 + tid];
    for (int i = tid; i < NS * BPC * COLS; i += RTHREADS) {
        ((float*)ghist)[i] = 0.f;
        ((float*)thist)[i] = 0.f;
    }
    __syncthreads();
    cluster_sync();   // all mbarriers initialized before any remote st.async

    // ---- P3 identities: thread owns col pair (2p, 2p+1), k-half ----
    const int pairIdx = tid & 255;
    const int khalf   = tid >> 8;
    const int gcol    = pairIdx * 2;
    const int gdst    = pairIdx >> 5;                // destination rank
    const uint32_t grd0 = mapa_u32(su32(&gpartB[rank][khalf][0][pairIdx & 31]), gdst);
    const uint32_t grd1 = mapa_u32(su32(&gpartB[rank][khalf][1][pairIdx & 31]), gdst);
    uint32_t grm[2];
    grm[0] = mapa_u32(mg_base + 0, gdst);
    grm[1] = mapa_u32(mg_base + 8, gdst);

    // W3 slice: 32 k-rows x 2 adjacent cols, pair-packed
    uint64_t w3p[32];
    #pragma unroll
    for (int kk = 0; kk < 32; kk++)
        w3p[kk] = *(const uint64_t*)&W3[(size_t)(col0 + khalf * 32 + kk) * D + gcol];

    // loader ids (warps 10-15)
    const int lidx = tid - 320;
    const int lrow = lidx >> 4;            // 0..11
    const int lq   = (lidx & 15) * 4;
    const int lbl  = (lidx >> 4) & 1;

    // P1 ids
    const int p1bl = (warp < 10) ? warp / NS : 0;
    const int p1i  = (warp < 10) ? warp % NS : 0;
    const int d0   = lane * 2;
    uint32_t spush[2];
    spush[0] = su32(&spart[0][p1bl][p1i][rank]);
    spush[1] = su32(&spart[1][p1bl][p1i][rank]);

    // htilde/softmax ids (warps 0-3)
    const int hbl = warp >> 1;
    const int hdd = ((warp & 1) << 5) + lane;

    // ---- prologue: load t=0 C/H rows ----
    if (warp >= 10) {
        if (lrow >= 10)
            *(float4*)&pbufC[0][lrow - 10][lq] =
                __ldcs((const float4*)&g_C[((size_t)(b0 + lrow - 10) * S + 0) * D + col0 + lq]);
        if (lidx < 32)
            *(float4*)&hbuf[0][lbl][lq] =
                *(const float4*)&Hm[((size_t)(b0 + lbl) * S + 0) * D + col0 + lq];
    }
    __syncthreads();

    // prologue P1-pre for t=0 (i<4 warps; all j<0 -> c-only)
    if (warp < 10 && p1i != NS - 1) {
        float2 c2 = *(float2*)&pbufC[0][p1bl][d0];
        float val = ftanh(c2.x) * vsm[d0] + ftanh(c2.y) * vsm[d0 + 1];
        val = warp_sum_all(val);
        if (lane < RANKS)
            stasync_b32(spush[0], msp_base + 0, lane, __float_as_uint(val));
    }

    // prologue: issue LDGs for t=1
    float4 pvA = make_float4(0.f, 0.f, 0.f, 0.f);
    float4 pvH = make_float4(0.f, 0.f, 0.f, 0.f);
    int pfrow = -1; bool pfH = false;
    if (warp >= 10) {
        if (lrow < 10) {
            int jbl = lrow / NS, ji = lrow % NS, j = 1 - NS + ji;
            if (j >= 0) {
                pvA = __ldcs((const float4*)&g_A[((size_t)(b0 + jbl) * S + j) * D + col0 + lq]);
                pfrow = lrow;
            }
        } else {
            pvA = __ldcs((const float4*)&g_C[((size_t)(b0 + lrow - 10) * S + 1) * D + col0 + lq]);
            pfrow = lrow;
        }
        if (lidx < 32) {
            pvH = *(const float4*)&Hm[((size_t)(b0 + lbl) * S + 1) * D + col0 + lq];
            pfH = true;
        }
    }

    for (int t = 0; t < S; t++) {
        const int par = t & 1;
        const int sk  = t & 3;

        // ---- critical warps (4, 9): wait g(t-1), sum, logit, push s_crit ----
        if (warp < 10 && p1i == NS - 1) {
            const int j = t - 1;
            if (j >= 0) {
                const int gb = j & 1;
                mbar_wait(mg_base + 8 * gb, (j >> 1) & 1);
                if (warp == 4 && lane == 0)   // re-arm for data t+1
                    mbar_arrive_expect(mg_base + 8 * gb, TX_G);
            }
            float2 c2 = *(float2*)&pbufC[par][p1bl][d0];
            float x0 = c2.x, x1 = c2.y;
            if (j >= 0) {
                float2 a2 = *(float2*)&pbufA[par][warp][d0];
                uint64_t s = 0ull;
                #pragma unroll
                for (int r = 0; r < RANKS; r++) {
                    s = add2(s, gpartB[r][0][p1bl][lane]);
                    s = add2(s, gpartB[r][1][p1bl][lane]);
                }
                float g0, g1;
                unpack2(s, g0, g1);
                *(float2*)&ghist[j % NS][p1bl][d0] = make_float2(g0, g1);
                x0 += a2.x + g0;
                x1 += a2.y + g1;
            }
            float val = ftanh(x0) * vsm[d0] + ftanh(x1) * vsm[d0 + 1];
            val = warp_sum_all(val);
            if (lane < RANKS)
                stasync_b32(spush[par], msc_base + 8 * sk, lane, __float_as_uint(val));
        }

        // ---- warps 0-3: pre-wait + partial softmax, crit-wait + fold, htilde ----
        if (warp < 4) {
            // early slots (pushed end of step t-1): likely fast-path wait
            mbar_wait(msp_base + 8 * sk, (t >> 2) & 1);
            if (warp == 0 && lane == 0)
                mbar_arrive_expect(msp_base + 8 * sk, TX_PRE);   // re-arm t+4

            float sv[NS - 1];
            #pragma unroll
            for (int i = 0; i < NS - 1; i++) {
                float4 u0 = *(float4*)&spart[par][hbl][i][0];
                float4 u1 = *(float4*)&spart[par][hbl][i][4];
                sv[i] = (u0.x + u0.y + u0.z + u0.w) + (u1.x + u1.y + u1.z + u1.w);
            }
            float m4 = sv[0];
            #pragma unroll
            for (int i = 1; i < NS - 1; i++) m4 = fmaxf(m4, sv[i]);
            float e[NS - 1], sum4 = 0.f;
            #pragma unroll
            for (int i = 0; i < NS - 1; i++) { e[i] = __expf(sv[i] - m4); sum4 += e[i]; }

            // late critical slot
            mbar_wait(msc_base + 8 * sk, (t >> 2) & 1);
            if (warp == 0 && lane == 0)
                mbar_arrive_expect(msc_base + 8 * sk, TX_CRIT);  // re-arm t+4
            float4 u0 = *(float4*)&spart[par][hbl][NS - 1][0];
            float4 u1 = *(float4*)&spart[par][hbl][NS - 1][4];
            float s4 = (u0.x + u0.y + u0.z + u0.w) + (u1.x + u1.y + u1.z + u1.w);

            float m   = fmaxf(m4, s4);
            float sc  = __expf(m4 - m);           // rescale for early slots
            float e4  = __expf(s4 - m);
            float inv = __fdividef(1.f, sum4 * sc + e4);
            float wsc = sc * inv;

            float hh = 0.f;
            #pragma unroll
            for (int i = 0; i < NS - 1; i++) {
                int j = t - NS + i;
                if (j >= 0) hh += (e[i] * wsc) * thist[j % NS][hbl][hdd];
            }
            {
                int j4 = t - 1;
                if (j4 >= 0) hh += (e4 * inv) * thist[j4 % NS][hbl][hdd];
            }
            float hv = hbuf[par][hbl][hdd] + fmaxf(hh, 0.f);
            thist[t % NS][hbl][hdd] = hv;
            *(float2*)((float*)&hts4[hdd] + 2 * hbl) = make_float2(hv, hv);
            __stcs(&out[((size_t)(b0 + hbl) * S + t) * D + col0 + hdd], hv);
        }

        // ---- loader warps: deposit t+1, issue LDG t+2 ----
        if (warp >= 10) {
            if (pfrow >= 0) {
                if (pfrow < 10) *(float4*)&pbufA[par ^ 1][pfrow][lq]      = pvA;
                else            *(float4*)&pbufC[par ^ 1][pfrow - 10][lq] = pvA;
            }
            if (pfH) *(float4*)&hbuf[par ^ 1][lbl][lq] = pvH;
            pfrow = -1; pfH = false;
            const int tload = t + 2;
            if (tload < S) {
                if (lrow < 10) {
                    int jbl = lrow / NS, ji = lrow % NS, j = tload - NS + ji;
                    if (j >= 0) {
                        pvA = __ldcs((const float4*)&g_A[((size_t)(b0 + jbl) * S + j) * D + col0 + lq]);
                        pfrow = lrow;
                    }
                } else {
                    pvA = __ldcs((const float4*)&g_C[((size_t)(b0 + lrow - 10) * S + tload) * D + col0 + lq]);
                    pfrow = lrow;
                }
                if (lidx < 32) {
                    pvH = *(const float4*)&Hm[((size_t)(b0 + lbl) * S + tload) * D + col0 + lq];
                    pfH = true;
                }
            }
        }
        __syncthreads();   // single block barrier per step: hts4 ready

        if (t < S - 1) {
            // ---- P3: partial g over k-half, 2 cols x 2 batches ----
            uint64_t acc0 = 0ull, acc1 = 0ull;
            #pragma unroll
            for (int kk = 0; kk < 32; kk++) {
                float4 h = hts4[khalf * 32 + kk];
                acc0 = fma2(pack2(h.x, h.y), w3p[kk], acc0);
                acc1 = fma2(pack2(h.z, h.w), w3p[kk], acc1);
            }
            stasync_b64_pre(grd0, grm[par], acc0);
            stasync_b64_pre(grd1, grm[par], acc1);

            // ---- P1-pre for t+1 (i<4 warps) ----
            if (warp < 10 && p1i != NS - 1) {
                float2 c2 = *(float2*)&pbufC[par ^ 1][p1bl][d0];
                float x0 = c2.x, x1 = c2.y;
                const int j = (t + 1) - NS + p1i;
                if (j >= 0) {
                    float2 a2 = *(float2*)&pbufA[par ^ 1][warp][d0];
                    float2 g2 = *(float2*)&ghist[j % NS][p1bl][d0];
                    x0 += a2.x + g2.x;
                    x1 += a2.y + g2.y;
                }
                float val = ftanh(x0) * vsm[d0] + ftanh(x1) * vsm[d0 + 1];
                val = warp_sum_all(val);
                if (lane < RANKS)
                    stasync_b32(spush[par ^ 1], msp_base + 8 * ((t + 1) & 3), lane,
                                __float_as_uint(val));
            }
        }
    }

    // Terminal cluster sync: no CTA exits while peers' remote stores could
    // still target its SMEM / mbarriers.
    cluster_sync();
}

// ============================================================
// Launch
// ============================================================
extern "C" void kernel_launch(void* const* d_in, const int* in_sizes, int n_in,
                              void* d_out, int out_size)
{
    (void)in_sizes; (void)n_in; (void)out_size;
    const float* H  = (const float*)d_in[0];
    const float* v  = (const float*)d_in[1];
    const float* W1 = (const float*)d_in[2];
    const float* W2 = (const float*)d_in[3];
    const float* W3 = (const float*)d_in[4];
    float* out = (float*)d_out;

    precompute_kernel<<<dim3((B * S) / PM, 8), 256>>>(H, W1, W2);
    recurrent_kernel<<<NCLUSTERS * RANKS, RTHREADS>>>(H, v, W3, out);
}